// round 10
// baseline (speedup 1.0000x reference)
#include <cuda_runtime.h>
#include <cuda_bf16.h>
#include <cstdint>
#include <math.h>

#define NB 32
#define NV 2048
#define NEDGE 12288
#define NNZ (NEDGE + NV)   // 14336 (edges + self loops)

// ================= helpers (plain sm_103-safe) =================
__device__ __forceinline__ uint32_t smem_to_u32(const void* smem_ptr) {
    uint32_t addr;
    asm("{ .reg .u64 tmp; cvta.to.shared.u64 tmp, %1; cvt.u32.u64 %0, tmp; }"
        : "=r"(addr) : "l"(smem_ptr));
    return addr;
}
#define SWZ(o) ((o) ^ (((o) >> 3) & 0x70))
#define CP_ASYNC16(dst, src) \
    asm volatile("cp.async.cg.shared.global [%0], [%1], 16;" :: "r"(dst), "l"(src))
#define CP_COMMIT asm volatile("cp.async.commit_group;" ::: "memory")
#define CP_WAIT_GROUP(n) asm volatile("cp.async.wait_group %0;" :: "n"(n) : "memory")
#define LDM4(r, addr) \
    asm volatile("ldmatrix.sync.aligned.m8n8.x4.shared.b16 {%0,%1,%2,%3}, [%4];" \
        : "=r"((r)[0]), "=r"((r)[1]), "=r"((r)[2]), "=r"((r)[3]) : "r"(addr))
#define MMA16816(d, a, b) \
    asm volatile("mma.sync.aligned.m16n8k16.row.col.f32.bf16.bf16.f32 " \
        "{%0,%1,%2,%3}, {%4,%5,%6,%7}, {%8,%9}, {%0,%1,%2,%3};" \
        : "+f"((d)[0]), "+f"((d)[1]), "+f"((d)[2]), "+f"((d)[3]) \
        : "r"((a)[0]), "r"((a)[1]), "r"((a)[2]), "r"((a)[3]), "r"((b)[0]), "r"((b)[1]))

// ---------------- scratch (device globals; no allocation) ----------------
__device__ float g_bufA[(size_t)NB * NV * 512];   // x2 bf16 plane
__device__ float g_bufB[(size_t)NB * NV * 512];   // t2 = A^2(x2) bf16
__device__ float g_s3a[NB * NV * 3];
__device__ float g_s3b[NB * NV * 3];
__device__ float g_s3c[NB * NV * 3];
__device__ float g_imgstage[NB * 512];
__device__ float g_imgterm[NB * 512];
__device__ __nv_bfloat16 g_W34T[512 * 512];       // W34 transposed [N,K] bf16
__device__ float g_W12c[3 * 512];
__device__ float g_W56[512 * 3];
__device__ float g_b1W2[512];
__device__ float g_b3W4[512];
__device__ float g_b5W6[3];
__device__ float g_s1[NV];
__device__ float g_s2[NV];
__device__ float g_dinv[NV];
__device__ float g_nrm[NNZ];
__device__ int   g_rowptr[NV + 1];
__device__ int   g_cols[NNZ];
__device__ int   g_counts[NV];
__device__ int   g_fill[NV];
__device__ float g_fch1[NB * 1024];
__device__ float g_fch2[NB * 1024];
__device__ float g_fcout[NB * 6144];

// ---------------- fused graph/CSR setup: ONE single-block kernel ----------------
__global__ void __launch_bounds__(1024) k_setup(const int* __restrict__ edge) {
    __shared__ int p[1024];
    int t = threadIdx.x;
    // init
    for (int i = t; i < NV; i += 1024) { g_counts[i] = 1; g_fill[i] = 0; }
    __syncthreads();
    // degree
    for (int e = t; e < NEDGE; e += 1024) atomicAdd(&g_counts[edge[NEDGE + e]], 1);
    __syncthreads();
    // scan + dinv
    int c0 = g_counts[2 * t], c1 = g_counts[2 * t + 1];
    g_dinv[2 * t]     = rsqrtf((float)c0);
    g_dinv[2 * t + 1] = rsqrtf((float)c1);
    p[t] = c0 + c1;
    __syncthreads();
    for (int off = 1; off < 1024; off <<= 1) {
        int v = (t >= off) ? p[t - off] : 0;
        __syncthreads();
        p[t] += v;
        __syncthreads();
    }
    int base = p[t] - (c0 + c1);
    g_rowptr[2 * t] = base;
    g_rowptr[2 * t + 1] = base + c0;
    if (t == 1023) g_rowptr[2048] = p[1023];
    __syncthreads();
    // fill CSR
    for (int i = t; i < NNZ; i += 1024) {
        if (i < NEDGE) {
            int s = edge[i], d = edge[NEDGE + i];
            int pos = g_rowptr[d] + atomicAdd(&g_fill[d], 1);
            g_cols[pos] = s;
            g_nrm[pos] = g_dinv[s] * g_dinv[d];
        } else {
            int v = i - NEDGE;
            int pos = g_rowptr[v] + atomicAdd(&g_fill[v], 1);
            g_cols[pos] = v;
            g_nrm[pos] = g_dinv[v] * g_dinv[v];
        }
    }
    __syncthreads();
    // s1
    for (int v = t; v < NV; v += 1024) {
        float s = 0.f;
        for (int j = g_rowptr[v]; j < g_rowptr[v + 1]; j++) s += g_nrm[j];
        g_s1[v] = s;
    }
    __syncthreads();
    // s2
    for (int v = t; v < NV; v += 1024) {
        float s = 0.f;
        for (int j = g_rowptr[v]; j < g_rowptr[v + 1]; j++) s += g_nrm[j] * g_s1[g_cols[j]];
        g_s2[v] = s;
    }
}

// ---------------- generic small matmul (imgstage/imgterm) ----------------
__global__ void k_smallmm(const float* __restrict__ A, const float* __restrict__ Bw,
                          float* __restrict__ C, int M, int K, int N, int strideA) {
    int i = blockIdx.x * blockDim.x + threadIdx.x;
    if (i >= M * N) return;
    int m = i / N, o = i - m * N;
    float acc = 0.f;
    const float* a = A + (size_t)m * strideA;
    for (int k = 0; k < K; k++) acc += a[k] * Bw[(size_t)k * N + o];
    C[i] = acc;
}

// ---------------- fused tiny weight-prep (W12c, b1W2, b3W4, W56, b5W6) ----------------
__global__ void k_prepsmall(const float* __restrict__ W1, const float* __restrict__ W2,
                            const float* __restrict__ b1, const float* __restrict__ b3,
                            const float* __restrict__ W4, const float* __restrict__ W5,
                            const float* __restrict__ W6, const float* __restrict__ b5) {
    int i = blockIdx.x * blockDim.x + threadIdx.x;
    if (i < 1536) {                       // W12c = W1[0:3] @ W2
        int m = i / 512, o = i - m * 512;
        float acc = 0.f;
        for (int k = 0; k < 512; k++) acc += W1[m * 512 + k] * W2[(size_t)k * 512 + o];
        g_W12c[i] = acc;
    } else if (i < 2048) {                // b1W2 = b1 @ W2
        int o = i - 1536;
        float acc = 0.f;
        for (int k = 0; k < 512; k++) acc += b1[k] * W2[(size_t)k * 512 + o];
        g_b1W2[o] = acc;
    } else if (i < 2560) {                // b3W4 = b3 @ W4
        int o = i - 2048;
        float acc = 0.f;
        for (int k = 0; k < 512; k++) acc += b3[k] * W4[(size_t)k * 512 + o];
        g_b3W4[o] = acc;
    } else if (i < 4096) {                // W56 = W5 @ W6
        int j = i - 2560;
        int m = j / 3, o = j - m * 3;
        float acc = 0.f;
        for (int k = 0; k < 64; k++) acc += W5[m * 64 + k] * W6[k * 3 + o];
        g_W56[j] = acc;
    } else if (i < 4099) {                // b5W6 = b5 @ W6
        int o = i - 4096;
        float acc = 0.f;
        for (int k = 0; k < 64; k++) acc += b5[k] * W6[k * 3 + o];
        g_b5W6[o] = acc;
    }
}

// ---------------- W34 = W3@W4, epilogue writes transposed bf16 directly ----------------
__global__ void __launch_bounds__(256) sgemm64T(const float* __restrict__ A,
                                                const float* __restrict__ Bw,
                                                int M, int N, int K) {
    __shared__ float As[16][64];
    __shared__ float Bs[16][68];
    int tid = threadIdx.x;
    int row0 = blockIdx.y * 64, col0 = blockIdx.x * 64;
    int aRow = tid >> 2, aCol = (tid & 3) * 4;
    int bRow = tid >> 4, bCol = (tid & 15) * 4;
    int tx = tid & 15, ty = tid >> 4;
    float acc[4][4];
#pragma unroll
    for (int i = 0; i < 4; i++)
#pragma unroll
        for (int j = 0; j < 4; j++) acc[i][j] = 0.f;
    for (int k0 = 0; k0 < K; k0 += 16) {
        float4 av = *(const float4*)&A[(size_t)(row0 + aRow) * K + k0 + aCol];
        float4 bv = *(const float4*)&Bw[(size_t)(k0 + bRow) * N + col0 + bCol];
        As[aCol + 0][aRow] = av.x;
        As[aCol + 1][aRow] = av.y;
        As[aCol + 2][aRow] = av.z;
        As[aCol + 3][aRow] = av.w;
        Bs[bRow][bCol + 0] = bv.x;
        Bs[bRow][bCol + 1] = bv.y;
        Bs[bRow][bCol + 2] = bv.z;
        Bs[bRow][bCol + 3] = bv.w;
        __syncthreads();
#pragma unroll
        for (int kk = 0; kk < 16; kk++) {
            float ar[4], br[4];
#pragma unroll
            for (int i = 0; i < 4; i++) ar[i] = As[kk][ty * 4 + i];
#pragma unroll
            for (int j = 0; j < 4; j++) br[j] = Bs[kk][tx * 4 + j];
#pragma unroll
            for (int i = 0; i < 4; i++)
#pragma unroll
                for (int j = 0; j < 4; j++) acc[i][j] = fmaf(ar[i], br[j], acc[i][j]);
        }
        __syncthreads();
    }
#pragma unroll
    for (int i = 0; i < 4; i++) {
        int krow = row0 + ty * 4 + i;
#pragma unroll
        for (int j = 0; j < 4; j++) {
            int ncol = col0 + tx * 4 + j;
            g_W34T[(size_t)ncol * 512 + krow] = __float2bfloat16(acc[i][j]);
        }
    }
}

// ---------------- fused two-hop F=3 aggregation (smem, one CTA per batch) ----------------
__global__ void __launch_bounds__(256) k_agg3two(const float* __restrict__ in,
                                                 float* __restrict__ out,
                                                 const float* __restrict__ biasA,
                                                 const float* __restrict__ biasB,
                                                 int relu) {
    __shared__ float sa[NV * 3];    // 24 KB
    __shared__ float sb[NV * 3];    // 24 KB  (total 48 KB = static limit)
    int b = blockIdx.x, t = threadIdx.x;
    const float* inb = in + (size_t)b * NV * 3;
    for (int i = t; i < NV * 3; i += 256) sa[i] = inb[i];
    __syncthreads();
    for (int v = t; v < NV; v += 256) {
        float a0 = 0.f, a1 = 0.f, a2 = 0.f;
        for (int j = g_rowptr[v]; j < g_rowptr[v + 1]; j++) {
            int s = g_cols[j]; float w = g_nrm[j];
            a0 = fmaf(w, sa[s * 3 + 0], a0);
            a1 = fmaf(w, sa[s * 3 + 1], a1);
            a2 = fmaf(w, sa[s * 3 + 2], a2);
        }
        sb[v * 3 + 0] = a0; sb[v * 3 + 1] = a1; sb[v * 3 + 2] = a2;
    }
    __syncthreads();
    float* ob = out + (size_t)b * NV * 3;
    for (int v = t; v < NV; v += 256) {
        float a0 = 0.f, a1 = 0.f, a2 = 0.f;
        for (int j = g_rowptr[v]; j < g_rowptr[v + 1]; j++) {
            int s = g_cols[j]; float w = g_nrm[j];
            a0 = fmaf(w, sb[s * 3 + 0], a0);
            a1 = fmaf(w, sb[s * 3 + 1], a1);
            a2 = fmaf(w, sb[s * 3 + 2], a2);
        }
        if (biasA) {
            float s1v = g_s1[v];
            a0 += s1v * biasA[0] + biasB[0];
            a1 += s1v * biasA[1] + biasB[1];
            a2 += s1v * biasA[2] + biasB[2];
        }
        if (relu) { a0 = fmaxf(0.f, a0); a1 = fmaxf(0.f, a1); a2 = fmaxf(0.f, a2); }
        ob[v * 3 + 0] = a0; ob[v * 3 + 1] = a1; ob[v * 3 + 2] = a2;
    }
}

// ---------------- x2 assembly -> bf16 plane ----------------
__global__ void k_x2(const float* __restrict__ b2, __nv_bfloat16* __restrict__ ahi) {
    int i = blockIdx.x * blockDim.x + threadIdx.x;       // over NB*NV*128 quads
    int og = i & 127;
    int bv = i >> 7;
    int v = bv & (NV - 1);
    int b = bv >> 11;
    float a0 = g_s3b[bv * 3 + 0], a1 = g_s3b[bv * 3 + 1], a2 = g_s3b[bv * 3 + 2];
    float4 w0 = ((const float4*)g_W12c)[0 * 128 + og];
    float4 w1 = ((const float4*)g_W12c)[1 * 128 + og];
    float4 w2 = ((const float4*)g_W12c)[2 * 128 + og];
    float4 it = ((const float4*)g_imgterm)[b * 128 + og];
    float4 bw = ((const float4*)g_b1W2)[og];
    float4 bb = ((const float4*)b2)[og];
    float s1v = g_s1[v], s2v = g_s2[v];
    float r[4];
    r[0] = fmaxf(0.f, a0 * w0.x + a1 * w1.x + a2 * w2.x + s2v * it.x + s1v * bw.x + bb.x);
    r[1] = fmaxf(0.f, a0 * w0.y + a1 * w1.y + a2 * w2.y + s2v * it.y + s1v * bw.y + bb.y);
    r[2] = fmaxf(0.f, a0 * w0.z + a1 * w1.z + a2 * w2.z + s2v * it.z + s1v * bw.z + bb.z);
    r[3] = fmaxf(0.f, a0 * w0.w + a1 * w1.w + a2 * w2.w + s2v * it.w + s1v * bw.w + bb.w);
    ushort4 hv;
    unsigned short* hp = &hv.x;
#pragma unroll
    for (int q = 0; q < 4; q++) {
        __nv_bfloat16 h = __float2bfloat16(r[q]);
        hp[q] = *(unsigned short*)&h;
    }
    ((ushort4*)ahi)[(size_t)bv * 128 + og] = hv;
}

// ---------------- fused two-hop aggregation: t2 = A^2(x2), smem-resident ----------------
#define AG_STRIDE 48
#define AG_SMEM   (NV * AG_STRIDE)   // 98304
__global__ void __launch_bounds__(1024) k_agg2hop(const __nv_bfloat16* __restrict__ x2,
                                                  __nv_bfloat16* __restrict__ t2) {
    extern __shared__ char sm[];
    int f0 = blockIdx.x * 16;
    int b  = blockIdx.y;
    int t  = threadIdx.x;
    const __nv_bfloat16* xb = x2 + (size_t)b * NV * 512 + f0;
    __nv_bfloat16* ob = t2 + (size_t)b * NV * 512 + f0;
#pragma unroll
    for (int r = 0; r < 2; r++) {
        int v = t + r * 1024;
        const uint4* src = (const uint4*)(xb + (size_t)v * 512);
        uint4* d = (uint4*)(sm + v * AG_STRIDE);
        d[0] = src[0]; d[1] = src[1];
    }
    __syncthreads();
    uint4 keep[2][2];
#pragma unroll
    for (int r = 0; r < 2; r++) {
        int v = t + r * 1024;
        float acc[16];
#pragma unroll
        for (int q = 0; q < 16; q++) acc[q] = 0.f;
        int beg = g_rowptr[v], end = g_rowptr[v + 1];
        for (int j = beg; j < end; j++) {
            int s = g_cols[j];
            float w = g_nrm[j];
            uint4 q0 = *(const uint4*)(sm + s * AG_STRIDE);
            uint4 q1 = *(const uint4*)(sm + s * AG_STRIDE + 16);
            const __nv_bfloat162* h0 = (const __nv_bfloat162*)&q0;
            const __nv_bfloat162* h1 = (const __nv_bfloat162*)&q1;
#pragma unroll
            for (int q = 0; q < 4; q++) {
                float2 f = __bfloat1622float2(h0[q]);
                acc[2 * q]     = fmaf(w, f.x, acc[2 * q]);
                acc[2 * q + 1] = fmaf(w, f.y, acc[2 * q + 1]);
                float2 g = __bfloat1622float2(h1[q]);
                acc[8 + 2 * q]     = fmaf(w, g.x, acc[8 + 2 * q]);
                acc[8 + 2 * q + 1] = fmaf(w, g.y, acc[8 + 2 * q + 1]);
            }
        }
        __nv_bfloat162* kp = (__nv_bfloat162*)keep[r];
#pragma unroll
        for (int q = 0; q < 8; q++) kp[q] = __floats2bfloat162_rn(acc[2 * q], acc[2 * q + 1]);
    }
    __syncthreads();
#pragma unroll
    for (int r = 0; r < 2; r++) {
        int v = t + r * 1024;
        uint4* d = (uint4*)(sm + v * AG_STRIDE);
        d[0] = keep[r][0]; d[1] = keep[r][1];
    }
    __syncthreads();
#pragma unroll
    for (int r = 0; r < 2; r++) {
        int v = t + r * 1024;
        float acc[16];
#pragma unroll
        for (int q = 0; q < 16; q++) acc[q] = 0.f;
        int beg = g_rowptr[v], end = g_rowptr[v + 1];
        for (int j = beg; j < end; j++) {
            int s = g_cols[j];
            float w = g_nrm[j];
            uint4 q0 = *(const uint4*)(sm + s * AG_STRIDE);
            uint4 q1 = *(const uint4*)(sm + s * AG_STRIDE + 16);
            const __nv_bfloat162* h0 = (const __nv_bfloat162*)&q0;
            const __nv_bfloat162* h1 = (const __nv_bfloat162*)&q1;
#pragma unroll
            for (int q = 0; q < 4; q++) {
                float2 f = __bfloat1622float2(h0[q]);
                acc[2 * q]     = fmaf(w, f.x, acc[2 * q]);
                acc[2 * q + 1] = fmaf(w, f.y, acc[2 * q + 1]);
                float2 g = __bfloat1622float2(h1[q]);
                acc[8 + 2 * q]     = fmaf(w, g.x, acc[8 + 2 * q]);
                acc[8 + 2 * q + 1] = fmaf(w, g.y, acc[8 + 2 * q + 1]);
            }
        }
        uint4 pk[2];
        __nv_bfloat162* pp = (__nv_bfloat162*)pk;
#pragma unroll
        for (int q = 0; q < 8; q++) pp[q] = __floats2bfloat162_rn(acc[2 * q], acc[2 * q + 1]);
        uint4* d = (uint4*)(ob + (size_t)v * 512);
        d[0] = pk[0]; d[1] = pk[1];
    }
}

// ---------------- mma.sync bf16 GEMM + fused bias/relu/W56-projection epilogue ----------------
// 5-stage cp.async pipeline (80 KB), prefetch distance 4, 2 CTAs/SM.
#define GM_STAGES 5
__global__ void __launch_bounds__(256, 2) gemm_mma(
    const uint4* __restrict__ Ah, const uint4* __restrict__ Bh,
    const float* __restrict__ b4) {
    extern __shared__ char smem[];
    uint32_t sb = smem_to_u32(smem);
    int tid = threadIdx.x, lane = tid & 31, wid = tid >> 5;
    int wr = wid & 3, wc = wid >> 2;
    int row0 = blockIdx.y << 7, col0 = blockIdx.x << 7;

    auto load_chunk = [&](int kc, int stage) {
        uint32_t st = sb + stage * 16384;
#pragma unroll
        for (int i = tid; i < 512; i += 256) {
            int r = i >> 2, c = i & 3;
            uint32_t soff = SWZ(r * 64 + c * 16);
            size_t ga = (size_t)(row0 + r) * 64 + kc * 4 + c;
            size_t gb = (size_t)(col0 + r) * 64 + kc * 4 + c;
            CP_ASYNC16(st + soff,        (const void*)(Ah + ga));
            CP_ASYNC16(st + 8192 + soff, (const void*)(Bh + gb));
        }
    };

    load_chunk(0, 0); CP_COMMIT;
    load_chunk(1, 1); CP_COMMIT;
    load_chunk(2, 2); CP_COMMIT;
    load_chunk(3, 3); CP_COMMIT;

    float acc[2][8][4];
#pragma unroll
    for (int mt = 0; mt < 2; mt++)
#pragma unroll
        for (int nt = 0; nt < 8; nt++)
#pragma unroll
            for (int q = 0; q < 4; q++) acc[mt][nt][q] = 0.f;

    int stage = 0;
    for (int kc = 0; kc < 16; kc++) {
        CP_WAIT_GROUP(3);          // chunk kc resident
        __syncthreads();           // stage (kc-1)%5 consumption finished -> reusable
        if (kc + 4 < 16) {
            int ws = stage + 4; if (ws >= GM_STAGES) ws -= GM_STAGES;
            load_chunk(kc + 4, ws);
        }
        CP_COMMIT;
        uint32_t base = sb + stage * 16384;
        if (++stage == GM_STAGES) stage = 0;
#pragma unroll
        for (int ks = 0; ks < 2; ks++) {
            uint32_t ah[2][4];
#pragma unroll
            for (int mt = 0; mt < 2; mt++) {
                int r = wr * 32 + mt * 16 + (lane & 15);
                uint32_t off = SWZ(r * 64 + ks * 32 + ((lane >> 4) << 4));
                LDM4(ah[mt], base + off);
            }
#pragma unroll
            for (int nt2 = 0; nt2 < 4; nt2++) {
                int nrow = wc * 64 + nt2 * 16 + (lane & 7) + ((lane >> 4) << 3);
                uint32_t off = SWZ(nrow * 64 + ks * 32 + (((lane >> 3) & 1) << 4));
                uint32_t bhf[4];
                LDM4(bhf, base + 8192 + off);
#pragma unroll
                for (int h = 0; h < 2; h++) {
                    uint32_t bh2[2] = { bhf[2 * h], bhf[2 * h + 1] };
                    int nt = 2 * nt2 + h;
#pragma unroll
                    for (int mt = 0; mt < 2; mt++)
                        MMA16816(acc[mt][nt], ah[mt], bh2);
                }
            }
        }
    }

    // --- epilogue: bias + relu + W56 projection, atomicAdd into s3a ---
    float p[4][3];
#pragma unroll
    for (int r = 0; r < 4; r++) { p[r][0] = 0.f; p[r][1] = 0.f; p[r][2] = 0.f; }
    int R = row0 + wr * 32 + (lane >> 2);
    float s1r[4];
#pragma unroll
    for (int r = 0; r < 4; r++)
        s1r[r] = g_s1[(R + ((r >> 1) << 4) + ((r & 1) << 3)) & (NV - 1)];
#pragma unroll
    for (int mt = 0; mt < 2; mt++) {
#pragma unroll
        for (int nt = 0; nt < 8; nt++) {
            int c = col0 + wc * 64 + nt * 8 + ((lane & 3) << 1);
            float bw0 = g_b3W4[c],     bc0 = b4[c];
            float bw1 = g_b3W4[c + 1], bc1 = b4[c + 1];
            float wa0 = g_W56[c * 3 + 0], wa1 = g_W56[c * 3 + 1], wa2 = g_W56[c * 3 + 2];
            float wb0 = g_W56[(c + 1) * 3 + 0], wb1 = g_W56[(c + 1) * 3 + 1], wb2 = g_W56[(c + 1) * 3 + 2];
            int ra = mt * 2, rb = mt * 2 + 1;
            float u;
            u = fmaxf(0.f, acc[mt][nt][0] + s1r[ra] * bw0 + bc0);
            p[ra][0] = fmaf(u, wa0, p[ra][0]); p[ra][1] = fmaf(u, wa1, p[ra][1]); p[ra][2] = fmaf(u, wa2, p[ra][2]);
            u = fmaxf(0.f, acc[mt][nt][1] + s1r[ra] * bw1 + bc1);
            p[ra][0] = fmaf(u, wb0, p[ra][0]); p[ra][1] = fmaf(u, wb1, p[ra][1]); p[ra][2] = fmaf(u, wb2, p[ra][2]);
            u = fmaxf(0.f, acc[mt][nt][2] + s1r[rb] * bw0 + bc0);
            p[rb][0] = fmaf(u, wa0, p[rb][0]); p[rb][1] = fmaf(u, wa1, p[rb][1]); p[rb][2] = fmaf(u, wa2, p[rb][2]);
            u = fmaxf(0.f, acc[mt][nt][3] + s1r[rb] * bw1 + bc1);
            p[rb][0] = fmaf(u, wb0, p[rb][0]); p[rb][1] = fmaf(u, wb1, p[rb][1]); p[rb][2] = fmaf(u, wb2, p[rb][2]);
        }
    }
#pragma unroll
    for (int r = 0; r < 4; r++)
#pragma unroll
        for (int k = 0; k < 3; k++) {
            p[r][k] += __shfl_xor_sync(0xffffffffu, p[r][k], 1);
            p[r][k] += __shfl_xor_sync(0xffffffffu, p[r][k], 2);
        }
    if ((lane & 3) == 0) {
#pragma unroll
        for (int r = 0; r < 4; r++) {
            int m = R + ((r >> 1) << 4) + ((r & 1) << 3);
            atomicAdd(&g_s3a[(size_t)m * 3 + 0], p[r][0]);
            atomicAdd(&g_s3a[(size_t)m * 3 + 1], p[r][1]);
            atomicAdd(&g_s3a[(size_t)m * 3 + 2], p[r][2]);
        }
    }
}

// ---------------- FC head: fused bias init + s3a zero; split-K GEMMs with atomics ----------------
__global__ void k_cinitz(const float* __restrict__ fcb1, const float* __restrict__ fcb2,
                         const float* __restrict__ fcb3) {
    int i = blockIdx.x * blockDim.x + threadIdx.x;   // 196608 threads
    if (i < 32 * 1024) {
        g_fch1[i] = fcb1[i & 1023];
        g_fch2[i] = fcb2[i & 1023];
    }
    if (i < 32 * 6144) {
        g_fcout[i] = fcb3[i % 6144];
        g_s3a[i] = 0.f;
    }
}

__global__ void __launch_bounds__(256) fcgemm_sk(const float* __restrict__ A,
                                                 const float* __restrict__ W,
                                                 float* __restrict__ C,
                                                 int K, int N, int Kc) {
    __shared__ float As[32][33];
    int tid = threadIdx.x;
    int o = blockIdx.x * 64 + (tid & 63);
    int bg = (tid >> 6) * 8;
    int k0base = blockIdx.y * Kc;
    float acc[8];
#pragma unroll
    for (int r = 0; r < 8; r++) acc[r] = 0.f;
    for (int k0 = k0base; k0 < k0base + Kc; k0 += 32) {
#pragma unroll
        for (int l = 0; l < 4; l++) {
            int idx = tid + 256 * l;
            int r = idx >> 5, kk = idx & 31;
            As[r][kk] = A[(size_t)r * K + k0 + kk];
        }
        __syncthreads();
#pragma unroll 8
        for (int kk = 0; kk < 32; kk++) {
            float w = W[(size_t)(k0 + kk) * N + o];
#pragma unroll
            for (int r = 0; r < 8; r++) acc[r] = fmaf(As[bg + r][kk], w, acc[r]);
        }
        __syncthreads();
    }
#pragma unroll
    for (int r = 0; r < 8; r++) atomicAdd(&C[(size_t)(bg + r) * N + o], acc[r]);
}

// ---------------- final: out = verts + 0.1*tanh(fcout) ----------------
__global__ void k_final(const float* __restrict__ verts, float* __restrict__ out) {
    int i = blockIdx.x * blockDim.x + threadIdx.x;
    if (i >= NB * NV * 3) return;
    out[i] = verts[i] + 0.1f * tanhf(g_fcout[i]);
}

// ---------------- host launcher ----------------
extern "C" void kernel_launch(void* const* d_in, const int* in_sizes, int n_in,
                              void* d_out, int out_size) {
    const float* verts = (const float*)d_in[0];
    const float* img   = (const float*)d_in[1];
    const int*   edge  = (const int*)d_in[2];
    const float* W1 = (const float*)d_in[3];   const float* b1 = (const float*)d_in[4];
    const float* W2 = (const float*)d_in[5];   const float* b2 = (const float*)d_in[6];
    const float* W3 = (const float*)d_in[7];   const float* b3 = (const float*)d_in[8];
    const float* W4 = (const float*)d_in[9];   const float* b4 = (const float*)d_in[10];
    const float* W5 = (const float*)d_in[11];  const float* b5 = (const float*)d_in[12];
    const float* W6 = (const float*)d_in[13];  const float* b6 = (const float*)d_in[14];
    const float* fcW1 = (const float*)d_in[15]; const float* fcb1 = (const float*)d_in[16];
    const float* fcW2 = (const float*)d_in[17]; const float* fcb2 = (const float*)d_in[18];
    const float* fcW3 = (const float*)d_in[19]; const float* fcb3 = (const float*)d_in[20];
    float* out = (float*)d_out;

    float *bufA, *bufB, *s3a, *s3b, *s3c, *imgstage, *imgterm, *b5W6;
    float *fch1, *fch2, *fcout;
    __nv_bfloat16 *w34t;
    cudaGetSymbolAddress((void**)&bufA, g_bufA);
    cudaGetSymbolAddress((void**)&bufB, g_bufB);
    cudaGetSymbolAddress((void**)&s3a, g_s3a);
    cudaGetSymbolAddress((void**)&s3b, g_s3b);
    cudaGetSymbolAddress((void**)&s3c, g_s3c);
    cudaGetSymbolAddress((void**)&imgstage, g_imgstage);
    cudaGetSymbolAddress((void**)&imgterm, g_imgterm);
    cudaGetSymbolAddress((void**)&w34t, g_W34T);
    cudaGetSymbolAddress((void**)&b5W6, g_b5W6);
    cudaGetSymbolAddress((void**)&fch1, g_fch1);
    cudaGetSymbolAddress((void**)&fch2, g_fch2);
    cudaGetSymbolAddress((void**)&fcout, g_fcout);

    __nv_bfloat16* x2h = (__nv_bfloat16*)bufA;
    __nv_bfloat16* t2h = (__nv_bfloat16*)bufB;

    cudaFuncSetAttribute(gemm_mma, cudaFuncAttributeMaxDynamicSharedMemorySize,
                         GM_STAGES * 16384);
    cudaFuncSetAttribute(k_agg2hop, cudaFuncAttributeMaxDynamicSharedMemorySize, AG_SMEM);

    // 1: CSR + norms (single fused kernel)
    k_setup<<<1, 1024>>>(edge);
    // 2: FC bias init + s3a zero (independent)
    k_cinitz<<<768, 256>>>(fcb1, fcb2, fcb3);
    // 3-6: weight precompute
    k_prepsmall<<<17, 256>>>(W1, W2, b1, b3, W4, W5, W6, b5);
    k_smallmm<<<64, 256>>>(img, W1 + 3 * 512, imgstage, NB, 512, 512, 512);
    k_smallmm<<<64, 256>>>(imgstage, W2, imgterm, NB, 512, 512, 512);
    sgemm64T<<<dim3(8, 8), 256>>>(W3, W4, 512, 512, 512);
    // 7: layers 1+2 two-hop on vertices (F=3)
    k_agg3two<<<32, 256>>>(verts, s3b, NULL, NULL, 0);
    // 8: x2 assembly
    k_x2<<<32768, 256>>>(b2, x2h);
    // 9: t2 = A^2(x2)
    k_agg2hop<<<dim3(32, 32), 1024, AG_SMEM>>>(x2h, t2h);
    // 10: GEMM + bias/relu/W56 projection -> s3a
    gemm_mma<<<dim3(4, 512), 256, GM_STAGES * 16384>>>((const uint4*)t2h, (const uint4*)w34t, b4);
    // 11: layers 5+6 two-hop (F=3, bias+relu)
    k_agg3two<<<32, 256>>>(s3a, s3c, b5W6, b6, 1);
    // 12-14: FC head
    fcgemm_sk<<<dim3(16, 24), 256>>>(s3c, fcW1, fch1, 6144, 1024, 256);
    fcgemm_sk<<<dim3(16, 8), 256>>>(fch1, fcW2, fch2, 1024, 1024, 128);
    fcgemm_sk<<<dim3(96, 4), 256>>>(fch2, fcW3, fcout, 1024, 6144, 256);
    // 15: output
    k_final<<<768, 256>>>(verts, out);
}

// round 11
// speedup vs baseline: 1.0035x; 1.0035x over previous
#include <cuda_runtime.h>
#include <cuda_bf16.h>
#include <cstdint>
#include <math.h>

#define NB 32
#define NV 2048
#define NEDGE 12288
#define NNZ (NEDGE + NV)   // 14336 (edges + self loops)

// ================= helpers (plain sm_103-safe) =================
__device__ __forceinline__ uint32_t smem_to_u32(const void* smem_ptr) {
    uint32_t addr;
    asm("{ .reg .u64 tmp; cvta.to.shared.u64 tmp, %1; cvt.u32.u64 %0, tmp; }"
        : "=r"(addr) : "l"(smem_ptr));
    return addr;
}
#define SWZ(o) ((o) ^ (((o) >> 3) & 0x70))
#define CP_ASYNC16(dst, src) \
    asm volatile("cp.async.cg.shared.global [%0], [%1], 16;" :: "r"(dst), "l"(src))
#define CP_COMMIT asm volatile("cp.async.commit_group;" ::: "memory")
#define CP_WAIT_GROUP(n) asm volatile("cp.async.wait_group %0;" :: "n"(n) : "memory")
#define LDM4(r, addr) \
    asm volatile("ldmatrix.sync.aligned.m8n8.x4.shared.b16 {%0,%1,%2,%3}, [%4];" \
        : "=r"((r)[0]), "=r"((r)[1]), "=r"((r)[2]), "=r"((r)[3]) : "r"(addr))
#define MMA16816(d, a, b) \
    asm volatile("mma.sync.aligned.m16n8k16.row.col.f32.bf16.bf16.f32 " \
        "{%0,%1,%2,%3}, {%4,%5,%6,%7}, {%8,%9}, {%0,%1,%2,%3};" \
        : "+f"((d)[0]), "+f"((d)[1]), "+f"((d)[2]), "+f"((d)[3]) \
        : "r"((a)[0]), "r"((a)[1]), "r"((a)[2]), "r"((a)[3]), "r"((b)[0]), "r"((b)[1]))

// ---------------- scratch (device globals; no allocation) ----------------
__device__ float g_bufA[(size_t)NB * NV * 512];   // x2 bf16 plane
__device__ float g_bufB[(size_t)NB * NV * 512];   // t2 = A^2(x2) bf16
__device__ float g_s3a[NB * NV * 3];
__device__ float g_s3b[NB * NV * 3];
__device__ float g_s3c[NB * NV * 3];
__device__ float g_imgstage[NB * 512];
__device__ float g_imgterm[NB * 512];
__device__ __nv_bfloat16 g_W34T[512 * 512];       // W34 transposed [N,K] bf16
__device__ float g_W12c[3 * 512];
__device__ float g_W56[512 * 3];
__device__ float g_b1W2[512];
__device__ float g_b3W4[512];
__device__ float g_b5W6[3];
__device__ float g_s1[NV];
__device__ float g_s2[NV];
__device__ float g_dinv[NV];
__device__ float g_nrm[NNZ];
__device__ int   g_rowptr[NV + 1];
__device__ int   g_cols[NNZ];
__device__ int   g_counts[NV];
__device__ int   g_fill[NV];
__device__ float g_fch1[NB * 1024];
__device__ float g_fch2[NB * 1024];
__device__ float g_fcout[NB * 6144];

// ---------------- graph/CSR setup (separate parallel kernels — R9 proven) ----------------
__global__ void k_init() {
    int i = blockIdx.x * blockDim.x + threadIdx.x;
    if (i < NV) { g_counts[i] = 1; g_fill[i] = 0; }
}
__global__ void k_deg(const int* __restrict__ edge) {
    int e = blockIdx.x * blockDim.x + threadIdx.x;
    if (e < NEDGE) atomicAdd(&g_counts[edge[NEDGE + e]], 1);
}
__global__ void k_scan() {
    __shared__ int p[1024];
    int t = threadIdx.x;
    int c0 = g_counts[2 * t], c1 = g_counts[2 * t + 1];
    g_dinv[2 * t]     = rsqrtf((float)c0);
    g_dinv[2 * t + 1] = rsqrtf((float)c1);
    p[t] = c0 + c1;
    __syncthreads();
    for (int off = 1; off < 1024; off <<= 1) {
        int v = (t >= off) ? p[t - off] : 0;
        __syncthreads();
        p[t] += v;
        __syncthreads();
    }
    int base = p[t] - (c0 + c1);
    g_rowptr[2 * t] = base;
    g_rowptr[2 * t + 1] = base + c0;
    if (t == 1023) g_rowptr[2048] = p[1023];
}
__global__ void k_fill(const int* __restrict__ edge) {
    int i = blockIdx.x * blockDim.x + threadIdx.x;
    if (i < NEDGE) {
        int s = edge[i], d = edge[NEDGE + i];
        int pos = g_rowptr[d] + atomicAdd(&g_fill[d], 1);
        g_cols[pos] = s;
        g_nrm[pos] = g_dinv[s] * g_dinv[d];
    } else if (i < NNZ) {
        int v = i - NEDGE;
        int pos = g_rowptr[v] + atomicAdd(&g_fill[v], 1);
        g_cols[pos] = v;
        g_nrm[pos] = g_dinv[v] * g_dinv[v];
    }
}
__global__ void k_s1() {
    int v = blockIdx.x * blockDim.x + threadIdx.x;
    if (v >= NV) return;
    float s = 0.f;
    for (int j = g_rowptr[v]; j < g_rowptr[v + 1]; j++) s += g_nrm[j];
    g_s1[v] = s;
}
__global__ void k_s2() {
    int v = blockIdx.x * blockDim.x + threadIdx.x;
    if (v >= NV) return;
    float s = 0.f;
    for (int j = g_rowptr[v]; j < g_rowptr[v + 1]; j++) s += g_nrm[j] * g_s1[g_cols[j]];
    g_s2[v] = s;
}

// ---------------- fused tiny weight-prep (W12c, b1W2, b3W4, W56, b5W6) ----------------
__global__ void k_prepsmall(const float* __restrict__ W1, const float* __restrict__ W2,
                            const float* __restrict__ b1, const float* __restrict__ b3,
                            const float* __restrict__ W4, const float* __restrict__ W5,
                            const float* __restrict__ W6, const float* __restrict__ b5) {
    int i = blockIdx.x * blockDim.x + threadIdx.x;
    if (i < 1536) {                       // W12c = W1[0:3] @ W2
        int m = i / 512, o = i - m * 512;
        float acc = 0.f;
        for (int k = 0; k < 512; k++) acc += W1[m * 512 + k] * W2[(size_t)k * 512 + o];
        g_W12c[i] = acc;
    } else if (i < 2048) {                // b1W2 = b1 @ W2
        int o = i - 1536;
        float acc = 0.f;
        for (int k = 0; k < 512; k++) acc += b1[k] * W2[(size_t)k * 512 + o];
        g_b1W2[o] = acc;
    } else if (i < 2560) {                // b3W4 = b3 @ W4
        int o = i - 2048;
        float acc = 0.f;
        for (int k = 0; k < 512; k++) acc += b3[k] * W4[(size_t)k * 512 + o];
        g_b3W4[o] = acc;
    } else if (i < 4096) {                // W56 = W5 @ W6
        int j = i - 2560;
        int m = j / 3, o = j - m * 3;
        float acc = 0.f;
        for (int k = 0; k < 64; k++) acc += W5[m * 64 + k] * W6[k * 3 + o];
        g_W56[j] = acc;
    } else if (i < 4099) {                // b5W6 = b5 @ W6
        int o = i - 4096;
        float acc = 0.f;
        for (int k = 0; k < 64; k++) acc += b5[k] * W6[k * 3 + o];
        g_b5W6[o] = acc;
    }
}

// ---------------- fast small-M GEMM (direct store): C[32,N] = A[32,K] @ W[K,N] ----------------
__global__ void __launch_bounds__(256) fcgemm_plain(const float* __restrict__ A,
                                                    const float* __restrict__ W,
                                                    float* __restrict__ C,
                                                    int K, int N, int strideA) {
    __shared__ float As[32][33];
    int tid = threadIdx.x;
    int o = blockIdx.x * 64 + (tid & 63);
    int bg = (tid >> 6) * 8;
    float acc[8];
#pragma unroll
    for (int r = 0; r < 8; r++) acc[r] = 0.f;
    for (int k0 = 0; k0 < K; k0 += 32) {
#pragma unroll
        for (int l = 0; l < 4; l++) {
            int idx = tid + 256 * l;
            int r = idx >> 5, kk = idx & 31;
            As[r][kk] = A[(size_t)r * strideA + k0 + kk];
        }
        __syncthreads();
#pragma unroll 8
        for (int kk = 0; kk < 32; kk++) {
            float w = W[(size_t)(k0 + kk) * N + o];
#pragma unroll
            for (int r = 0; r < 8; r++) acc[r] = fmaf(As[bg + r][kk], w, acc[r]);
        }
        __syncthreads();
    }
#pragma unroll
    for (int r = 0; r < 8; r++) C[(size_t)(bg + r) * N + o] = acc[r];
}

// ---------------- W34 = W3@W4, epilogue writes transposed bf16 directly ----------------
__global__ void __launch_bounds__(256) sgemm64T(const float* __restrict__ A,
                                                const float* __restrict__ Bw,
                                                int M, int N, int K) {
    __shared__ float As[16][64];
    __shared__ float Bs[16][68];
    int tid = threadIdx.x;
    int row0 = blockIdx.y * 64, col0 = blockIdx.x * 64;
    int aRow = tid >> 2, aCol = (tid & 3) * 4;
    int bRow = tid >> 4, bCol = (tid & 15) * 4;
    int tx = tid & 15, ty = tid >> 4;
    float acc[4][4];
#pragma unroll
    for (int i = 0; i < 4; i++)
#pragma unroll
        for (int j = 0; j < 4; j++) acc[i][j] = 0.f;
    for (int k0 = 0; k0 < K; k0 += 16) {
        float4 av = *(const float4*)&A[(size_t)(row0 + aRow) * K + k0 + aCol];
        float4 bv = *(const float4*)&Bw[(size_t)(k0 + bRow) * N + col0 + bCol];
        As[aCol + 0][aRow] = av.x;
        As[aCol + 1][aRow] = av.y;
        As[aCol + 2][aRow] = av.z;
        As[aCol + 3][aRow] = av.w;
        Bs[bRow][bCol + 0] = bv.x;
        Bs[bRow][bCol + 1] = bv.y;
        Bs[bRow][bCol + 2] = bv.z;
        Bs[bRow][bCol + 3] = bv.w;
        __syncthreads();
#pragma unroll
        for (int kk = 0; kk < 16; kk++) {
            float ar[4], br[4];
#pragma unroll
            for (int i = 0; i < 4; i++) ar[i] = As[kk][ty * 4 + i];
#pragma unroll
            for (int j = 0; j < 4; j++) br[j] = Bs[kk][tx * 4 + j];
#pragma unroll
            for (int i = 0; i < 4; i++)
#pragma unroll
                for (int j = 0; j < 4; j++) acc[i][j] = fmaf(ar[i], br[j], acc[i][j]);
        }
        __syncthreads();
    }
#pragma unroll
    for (int i = 0; i < 4; i++) {
        int krow = row0 + ty * 4 + i;
#pragma unroll
        for (int j = 0; j < 4; j++) {
            int ncol = col0 + tx * 4 + j;
            g_W34T[(size_t)ncol * 512 + krow] = __float2bfloat16(acc[i][j]);
        }
    }
}

// ---------------- aggregation, F=3 (R9 proven parallel shape) ----------------
__global__ void k_agg3(const float* __restrict__ in, float* __restrict__ out,
                       const float* __restrict__ biasA, const float* __restrict__ biasB,
                       int relu) {
    int i = blockIdx.x * blockDim.x + threadIdx.x;
    if (i >= NB * NV) return;
    int v = i & (NV - 1);
    int b = i >> 11;
    float a0 = 0.f, a1 = 0.f, a2 = 0.f;
    int beg = g_rowptr[v], end = g_rowptr[v + 1];
    const float* base = in + (size_t)b * NV * 3;
    for (int j = beg; j < end; j++) {
        int s = g_cols[j];
        float w = g_nrm[j];
        const float* p = base + s * 3;
        a0 = fmaf(w, p[0], a0);
        a1 = fmaf(w, p[1], a1);
        a2 = fmaf(w, p[2], a2);
    }
    if (biasA) {
        float s1v = g_s1[v];
        a0 += s1v * biasA[0] + biasB[0];
        a1 += s1v * biasA[1] + biasB[1];
        a2 += s1v * biasA[2] + biasB[2];
    }
    if (relu) { a0 = fmaxf(0.f, a0); a1 = fmaxf(0.f, a1); a2 = fmaxf(0.f, a2); }
    float* o = out + (size_t)i * 3;
    o[0] = a0; o[1] = a1; o[2] = a2;
}

// ---------------- x2 assembly -> bf16 plane ----------------
__global__ void k_x2(const float* __restrict__ b2, __nv_bfloat16* __restrict__ ahi) {
    int i = blockIdx.x * blockDim.x + threadIdx.x;       // over NB*NV*128 quads
    int og = i & 127;
    int bv = i >> 7;
    int v = bv & (NV - 1);
    int b = bv >> 11;
    float a0 = g_s3b[bv * 3 + 0], a1 = g_s3b[bv * 3 + 1], a2 = g_s3b[bv * 3 + 2];
    float4 w0 = ((const float4*)g_W12c)[0 * 128 + og];
    float4 w1 = ((const float4*)g_W12c)[1 * 128 + og];
    float4 w2 = ((const float4*)g_W12c)[2 * 128 + og];
    float4 it = ((const float4*)g_imgterm)[b * 128 + og];
    float4 bw = ((const float4*)g_b1W2)[og];
    float4 bb = ((const float4*)b2)[og];
    float s1v = g_s1[v], s2v = g_s2[v];
    float r[4];
    r[0] = fmaxf(0.f, a0 * w0.x + a1 * w1.x + a2 * w2.x + s2v * it.x + s1v * bw.x + bb.x);
    r[1] = fmaxf(0.f, a0 * w0.y + a1 * w1.y + a2 * w2.y + s2v * it.y + s1v * bw.y + bb.y);
    r[2] = fmaxf(0.f, a0 * w0.z + a1 * w1.z + a2 * w2.z + s2v * it.z + s1v * bw.z + bb.z);
    r[3] = fmaxf(0.f, a0 * w0.w + a1 * w1.w + a2 * w2.w + s2v * it.w + s1v * bw.w + bb.w);
    ushort4 hv;
    unsigned short* hp = &hv.x;
#pragma unroll
    for (int q = 0; q < 4; q++) {
        __nv_bfloat16 h = __float2bfloat16(r[q]);
        hp[q] = *(unsigned short*)&h;
    }
    ((ushort4*)ahi)[(size_t)bv * 128 + og] = hv;
}

// ---------------- fused two-hop aggregation: t2 = A^2(x2), smem-resident ----------------
#define AG_STRIDE 48
#define AG_SMEM   (NV * AG_STRIDE)   // 98304
__global__ void __launch_bounds__(1024) k_agg2hop(const __nv_bfloat16* __restrict__ x2,
                                                  __nv_bfloat16* __restrict__ t2) {
    extern __shared__ char sm[];
    int f0 = blockIdx.x * 16;
    int b  = blockIdx.y;
    int t  = threadIdx.x;
    const __nv_bfloat16* xb = x2 + (size_t)b * NV * 512 + f0;
    __nv_bfloat16* ob = t2 + (size_t)b * NV * 512 + f0;
#pragma unroll
    for (int r = 0; r < 2; r++) {
        int v = t + r * 1024;
        const uint4* src = (const uint4*)(xb + (size_t)v * 512);
        uint4* d = (uint4*)(sm + v * AG_STRIDE);
        d[0] = src[0]; d[1] = src[1];
    }
    __syncthreads();
    uint4 keep[2][2];
#pragma unroll
    for (int r = 0; r < 2; r++) {
        int v = t + r * 1024;
        float acc[16];
#pragma unroll
        for (int q = 0; q < 16; q++) acc[q] = 0.f;
        int beg = g_rowptr[v], end = g_rowptr[v + 1];
        for (int j = beg; j < end; j++) {
            int s = g_cols[j];
            float w = g_nrm[j];
            uint4 q0 = *(const uint4*)(sm + s * AG_STRIDE);
            uint4 q1 = *(const uint4*)(sm + s * AG_STRIDE + 16);
            const __nv_bfloat162* h0 = (const __nv_bfloat162*)&q0;
            const __nv_bfloat162* h1 = (const __nv_bfloat162*)&q1;
#pragma unroll
            for (int q = 0; q < 4; q++) {
                float2 f = __bfloat1622float2(h0[q]);
                acc[2 * q]     = fmaf(w, f.x, acc[2 * q]);
                acc[2 * q + 1] = fmaf(w, f.y, acc[2 * q + 1]);
                float2 g = __bfloat1622float2(h1[q]);
                acc[8 + 2 * q]     = fmaf(w, g.x, acc[8 + 2 * q]);
                acc[8 + 2 * q + 1] = fmaf(w, g.y, acc[8 + 2 * q + 1]);
            }
        }
        __nv_bfloat162* kp = (__nv_bfloat162*)keep[r];
#pragma unroll
        for (int q = 0; q < 8; q++) kp[q] = __floats2bfloat162_rn(acc[2 * q], acc[2 * q + 1]);
    }
    __syncthreads();
#pragma unroll
    for (int r = 0; r < 2; r++) {
        int v = t + r * 1024;
        uint4* d = (uint4*)(sm + v * AG_STRIDE);
        d[0] = keep[r][0]; d[1] = keep[r][1];
    }
    __syncthreads();
#pragma unroll
    for (int r = 0; r < 2; r++) {
        int v = t + r * 1024;
        float acc[16];
#pragma unroll
        for (int q = 0; q < 16; q++) acc[q] = 0.f;
        int beg = g_rowptr[v], end = g_rowptr[v + 1];
        for (int j = beg; j < end; j++) {
            int s = g_cols[j];
            float w = g_nrm[j];
            uint4 q0 = *(const uint4*)(sm + s * AG_STRIDE);
            uint4 q1 = *(const uint4*)(sm + s * AG_STRIDE + 16);
            const __nv_bfloat162* h0 = (const __nv_bfloat162*)&q0;
            const __nv_bfloat162* h1 = (const __nv_bfloat162*)&q1;
#pragma unroll
            for (int q = 0; q < 4; q++) {
                float2 f = __bfloat1622float2(h0[q]);
                acc[2 * q]     = fmaf(w, f.x, acc[2 * q]);
                acc[2 * q + 1] = fmaf(w, f.y, acc[2 * q + 1]);
                float2 g = __bfloat1622float2(h1[q]);
                acc[8 + 2 * q]     = fmaf(w, g.x, acc[8 + 2 * q]);
                acc[8 + 2 * q + 1] = fmaf(w, g.y, acc[8 + 2 * q + 1]);
            }
        }
        uint4 pk[2];
        __nv_bfloat162* pp = (__nv_bfloat162*)pk;
#pragma unroll
        for (int q = 0; q < 8; q++) pp[q] = __floats2bfloat162_rn(acc[2 * q], acc[2 * q + 1]);
        uint4* d = (uint4*)(ob + (size_t)v * 512);
        d[0] = pk[0]; d[1] = pk[1];
    }
}

// ---------------- mma.sync bf16 GEMM + fused bias/relu/W56-projection epilogue ----------------
// 4-stage cp.async pipeline (64 KB), prefetch distance 3, 2 CTAs/SM  (R8/R9 proven)
__global__ void __launch_bounds__(256, 2) gemm_mma(
    const uint4* __restrict__ Ah, const uint4* __restrict__ Bh,
    const float* __restrict__ b4) {
    extern __shared__ char smem[];
    uint32_t sb = smem_to_u32(smem);
    int tid = threadIdx.x, lane = tid & 31, wid = tid >> 5;
    int wr = wid & 3, wc = wid >> 2;
    int row0 = blockIdx.y << 7, col0 = blockIdx.x << 7;

    auto load_chunk = [&](int kc, int stage) {
        uint32_t st = sb + stage * 16384;
#pragma unroll
        for (int i = tid; i < 512; i += 256) {
            int r = i >> 2, c = i & 3;
            uint32_t soff = SWZ(r * 64 + c * 16);
            size_t ga = (size_t)(row0 + r) * 64 + kc * 4 + c;
            size_t gb = (size_t)(col0 + r) * 64 + kc * 4 + c;
            CP_ASYNC16(st + soff,        (const void*)(Ah + ga));
            CP_ASYNC16(st + 8192 + soff, (const void*)(Bh + gb));
        }
    };

    load_chunk(0, 0); CP_COMMIT;
    load_chunk(1, 1); CP_COMMIT;
    load_chunk(2, 2); CP_COMMIT;

    float acc[2][8][4];
#pragma unroll
    for (int mt = 0; mt < 2; mt++)
#pragma unroll
        for (int nt = 0; nt < 8; nt++)
#pragma unroll
            for (int q = 0; q < 4; q++) acc[mt][nt][q] = 0.f;

    for (int kc = 0; kc < 16; kc++) {
        CP_WAIT_GROUP(2);
        __syncthreads();
        if (kc + 3 < 16) load_chunk(kc + 3, (kc + 3) & 3);
        CP_COMMIT;
        uint32_t base = sb + (kc & 3) * 16384;
#pragma unroll
        for (int ks = 0; ks < 2; ks++) {
            uint32_t ah[2][4];
#pragma unroll
            for (int mt = 0; mt < 2; mt++) {
                int r = wr * 32 + mt * 16 + (lane & 15);
                uint32_t off = SWZ(r * 64 + ks * 32 + ((lane >> 4) << 4));
                LDM4(ah[mt], base + off);
            }
#pragma unroll
            for (int nt2 = 0; nt2 < 4; nt2++) {
                int nrow = wc * 64 + nt2 * 16 + (lane & 7) + ((lane >> 4) << 3);
                uint32_t off = SWZ(nrow * 64 + ks * 32 + (((lane >> 3) & 1) << 4));
                uint32_t bhf[4];
                LDM4(bhf, base + 8192 + off);
#pragma unroll
                for (int h = 0; h < 2; h++) {
                    uint32_t bh2[2] = { bhf[2 * h], bhf[2 * h + 1] };
                    int nt = 2 * nt2 + h;
#pragma unroll
                    for (int mt = 0; mt < 2; mt++)
                        MMA16816(acc[mt][nt], ah[mt], bh2);
                }
            }
        }
    }

    // --- epilogue: bias + relu + W56 projection, atomicAdd into s3a ---
    float p[4][3];
#pragma unroll
    for (int r = 0; r < 4; r++) { p[r][0] = 0.f; p[r][1] = 0.f; p[r][2] = 0.f; }
    int R = row0 + wr * 32 + (lane >> 2);
    float s1r[4];
#pragma unroll
    for (int r = 0; r < 4; r++)
        s1r[r] = g_s1[(R + ((r >> 1) << 4) + ((r & 1) << 3)) & (NV - 1)];
#pragma unroll
    for (int mt = 0; mt < 2; mt++) {
#pragma unroll
        for (int nt = 0; nt < 8; nt++) {
            int c = col0 + wc * 64 + nt * 8 + ((lane & 3) << 1);
            float bw0 = g_b3W4[c],     bc0 = b4[c];
            float bw1 = g_b3W4[c + 1], bc1 = b4[c + 1];
            float wa0 = g_W56[c * 3 + 0], wa1 = g_W56[c * 3 + 1], wa2 = g_W56[c * 3 + 2];
            float wb0 = g_W56[(c + 1) * 3 + 0], wb1 = g_W56[(c + 1) * 3 + 1], wb2 = g_W56[(c + 1) * 3 + 2];
            int ra = mt * 2, rb = mt * 2 + 1;
            float u;
            u = fmaxf(0.f, acc[mt][nt][0] + s1r[ra] * bw0 + bc0);
            p[ra][0] = fmaf(u, wa0, p[ra][0]); p[ra][1] = fmaf(u, wa1, p[ra][1]); p[ra][2] = fmaf(u, wa2, p[ra][2]);
            u = fmaxf(0.f, acc[mt][nt][1] + s1r[ra] * bw1 + bc1);
            p[ra][0] = fmaf(u, wb0, p[ra][0]); p[ra][1] = fmaf(u, wb1, p[ra][1]); p[ra][2] = fmaf(u, wb2, p[ra][2]);
            u = fmaxf(0.f, acc[mt][nt][2] + s1r[rb] * bw0 + bc0);
            p[rb][0] = fmaf(u, wa0, p[rb][0]); p[rb][1] = fmaf(u, wa1, p[rb][1]); p[rb][2] = fmaf(u, wa2, p[rb][2]);
            u = fmaxf(0.f, acc[mt][nt][3] + s1r[rb] * bw1 + bc1);
            p[rb][0] = fmaf(u, wb0, p[rb][0]); p[rb][1] = fmaf(u, wb1, p[rb][1]); p[rb][2] = fmaf(u, wb2, p[rb][2]);
        }
    }
#pragma unroll
    for (int r = 0; r < 4; r++)
#pragma unroll
        for (int k = 0; k < 3; k++) {
            p[r][k] += __shfl_xor_sync(0xffffffffu, p[r][k], 1);
            p[r][k] += __shfl_xor_sync(0xffffffffu, p[r][k], 2);
        }
    if ((lane & 3) == 0) {
#pragma unroll
        for (int r = 0; r < 4; r++) {
            int m = R + ((r >> 1) << 4) + ((r & 1) << 3);
            atomicAdd(&g_s3a[(size_t)m * 3 + 0], p[r][0]);
            atomicAdd(&g_s3a[(size_t)m * 3 + 1], p[r][1]);
            atomicAdd(&g_s3a[(size_t)m * 3 + 2], p[r][2]);
        }
    }
}

// ---------------- FC head: fused bias init + s3a zero; split-K GEMMs with atomics ----------------
__global__ void k_cinitz(const float* __restrict__ fcb1, const float* __restrict__ fcb2,
                         const float* __restrict__ fcb3) {
    int i = blockIdx.x * blockDim.x + threadIdx.x;   // 196608 threads
    if (i < 32 * 1024) {
        g_fch1[i] = fcb1[i & 1023];
        g_fch2[i] = fcb2[i & 1023];
    }
    if (i < 32 * 6144) {
        g_fcout[i] = fcb3[i % 6144];
        g_s3a[i] = 0.f;
    }
}

__global__ void __launch_bounds__(256) fcgemm_sk(const float* __restrict__ A,
                                                 const float* __restrict__ W,
                                                 float* __restrict__ C,
                                                 int K, int N, int Kc) {
    __shared__ float As[32][33];
    int tid = threadIdx.x;
    int o = blockIdx.x * 64 + (tid & 63);
    int bg = (tid >> 6) * 8;
    int k0base = blockIdx.y * Kc;
    float acc[8];
#pragma unroll
    for (int r = 0; r < 8; r++) acc[r] = 0.f;
    for (int k0 = k0base; k0 < k0base + Kc; k0 += 32) {
#pragma unroll
        for (int l = 0; l < 4; l++) {
            int idx = tid + 256 * l;
            int r = idx >> 5, kk = idx & 31;
            As[r][kk] = A[(size_t)r * K + k0 + kk];
        }
        __syncthreads();
#pragma unroll 8
        for (int kk = 0; kk < 32; kk++) {
            float w = W[(size_t)(k0 + kk) * N + o];
#pragma unroll
            for (int r = 0; r < 8; r++) acc[r] = fmaf(As[bg + r][kk], w, acc[r]);
        }
        __syncthreads();
    }
#pragma unroll
    for (int r = 0; r < 8; r++) atomicAdd(&C[(size_t)(bg + r) * N + o], acc[r]);
}

// ---------------- final: out = verts + 0.1*tanh(fcout) ----------------
__global__ void k_final(const float* __restrict__ verts, float* __restrict__ out) {
    int i = blockIdx.x * blockDim.x + threadIdx.x;
    if (i >= NB * NV * 3) return;
    out[i] = verts[i] + 0.1f * tanhf(g_fcout[i]);
}

// ---------------- host launcher ----------------
extern "C" void kernel_launch(void* const* d_in, const int* in_sizes, int n_in,
                              void* d_out, int out_size) {
    const float* verts = (const float*)d_in[0];
    const float* img   = (const float*)d_in[1];
    const int*   edge  = (const int*)d_in[2];
    const float* W1 = (const float*)d_in[3];   const float* b1 = (const float*)d_in[4];
    const float* W2 = (const float*)d_in[5];   const float* b2 = (const float*)d_in[6];
    const float* W3 = (const float*)d_in[7];   const float* b3 = (const float*)d_in[8];
    const float* W4 = (const float*)d_in[9];   const float* b4 = (const float*)d_in[10];
    const float* W5 = (const float*)d_in[11];  const float* b5 = (const float*)d_in[12];
    const float* W6 = (const float*)d_in[13];  const float* b6 = (const float*)d_in[14];
    const float* fcW1 = (const float*)d_in[15]; const float* fcb1 = (const float*)d_in[16];
    const float* fcW2 = (const float*)d_in[17]; const float* fcb2 = (const float*)d_in[18];
    const float* fcW3 = (const float*)d_in[19]; const float* fcb3 = (const float*)d_in[20];
    float* out = (float*)d_out;

    float *bufA, *bufB, *s3a, *s3b, *s3c, *imgstage, *imgterm, *b5W6;
    float *fch1, *fch2, *fcout;
    __nv_bfloat16 *w34t;
    cudaGetSymbolAddress((void**)&bufA, g_bufA);
    cudaGetSymbolAddress((void**)&bufB, g_bufB);
    cudaGetSymbolAddress((void**)&s3a, g_s3a);
    cudaGetSymbolAddress((void**)&s3b, g_s3b);
    cudaGetSymbolAddress((void**)&s3c, g_s3c);
    cudaGetSymbolAddress((void**)&imgstage, g_imgstage);
    cudaGetSymbolAddress((void**)&imgterm, g_imgterm);
    cudaGetSymbolAddress((void**)&w34t, g_W34T);
    cudaGetSymbolAddress((void**)&b5W6, g_b5W6);
    cudaGetSymbolAddress((void**)&fch1, g_fch1);
    cudaGetSymbolAddress((void**)&fch2, g_fch2);
    cudaGetSymbolAddress((void**)&fcout, g_fcout);

    __nv_bfloat16* x2h = (__nv_bfloat16*)bufA;
    __nv_bfloat16* t2h = (__nv_bfloat16*)bufB;

    cudaFuncSetAttribute(gemm_mma, cudaFuncAttributeMaxDynamicSharedMemorySize, 65536);
    cudaFuncSetAttribute(k_agg2hop, cudaFuncAttributeMaxDynamicSharedMemorySize, AG_SMEM);

    // --- graph/CSR + norm (parallel small kernels) ---
    k_init<<<8, 256>>>();
    k_deg<<<48, 256>>>(edge);
    k_scan<<<1, 1024>>>();
    k_fill<<<56, 256>>>(edge);
    k_s1<<<8, 256>>>();
    k_s2<<<8, 256>>>();
    k_cinitz<<<768, 256>>>(fcb1, fcb2, fcb3);

    // --- weight precompute ---
    k_prepsmall<<<17, 256>>>(W1, W2, b1, b3, W4, W5, W6, b5);
    fcgemm_plain<<<8, 256>>>(img, W1 + 3 * 512, imgstage, 512, 512, 512);
    fcgemm_plain<<<8, 256>>>(imgstage, W2, imgterm, 512, 512, 512);
    sgemm64T<<<dim3(8, 8), 256>>>(W3, W4, 512, 512, 512);

    // --- layers 1+2 fused ---
    k_agg3<<<256, 256>>>(verts, s3c, NULL, NULL, 0);
    k_agg3<<<256, 256>>>(s3c, s3b, NULL, NULL, 0);
    k_x2<<<32768, 256>>>(b2, x2h);

    // --- layers 3+4: t2 = A^2(x2), then GEMM w/ proj epilogue -> s3a ---
    k_agg2hop<<<dim3(32, 32), 1024, AG_SMEM>>>(x2h, t2h);
    gemm_mma<<<dim3(4, 512), 256, 65536>>>((const uint4*)t2h, (const uint4*)w34t, b4);

    // --- layers 5+6 remainder: A^2 on F=3 + bias + relu ---
    k_agg3<<<256, 256>>>(s3a, s3b, NULL, NULL, 0);
    k_agg3<<<256, 256>>>(s3b, s3c, b5W6, b6, 1);

    // --- FC head (deep split-K + atomics) ---
    fcgemm_sk<<<dim3(16, 24), 256>>>(s3c, fcW1, fch1, 6144, 1024, 256);
    fcgemm_sk<<<dim3(16, 8), 256>>>(fch1, fcW2, fch2, 1024, 1024, 128);
    fcgemm_sk<<<dim3(96, 4), 256>>>(fch2, fcW3, fcout, 1024, 6144, 256);

    // --- output ---
    k_final<<<768, 256>>>(verts, out);
}

// round 12
// speedup vs baseline: 1.0596x; 1.0559x over previous
#include <cuda_runtime.h>
#include <cuda_bf16.h>
#include <cstdint>
#include <math.h>

#define NB 32
#define NV 2048
#define NEDGE 12288
#define NNZ (NEDGE + NV)   // 14336 (edges + self loops)

// ================= helpers (plain sm_103-safe) =================
__device__ __forceinline__ uint32_t smem_to_u32(const void* smem_ptr) {
    uint32_t addr;
    asm("{ .reg .u64 tmp; cvta.to.shared.u64 tmp, %1; cvt.u32.u64 %0, tmp; }"
        : "=r"(addr) : "l"(smem_ptr));
    return addr;
}
#define SWZ(o) ((o) ^ (((o) >> 3) & 0x70))
#define CP_ASYNC16(dst, src) \
    asm volatile("cp.async.cg.shared.global [%0], [%1], 16;" :: "r"(dst), "l"(src))
#define CP_COMMIT asm volatile("cp.async.commit_group;" ::: "memory")
#define CP_WAIT_GROUP(n) asm volatile("cp.async.wait_group %0;" :: "n"(n) : "memory")
#define LDM4(r, addr) \
    asm volatile("ldmatrix.sync.aligned.m8n8.x4.shared.b16 {%0,%1,%2,%3}, [%4];" \
        : "=r"((r)[0]), "=r"((r)[1]), "=r"((r)[2]), "=r"((r)[3]) : "r"(addr))
#define MMA16816(d, a, b) \
    asm volatile("mma.sync.aligned.m16n8k16.row.col.f32.bf16.bf16.f32 " \
        "{%0,%1,%2,%3}, {%4,%5,%6,%7}, {%8,%9}, {%0,%1,%2,%3};" \
        : "+f"((d)[0]), "+f"((d)[1]), "+f"((d)[2]), "+f"((d)[3]) \
        : "r"((a)[0]), "r"((a)[1]), "r"((a)[2]), "r"((a)[3]), "r"((b)[0]), "r"((b)[1]))

// ---------------- scratch (device globals; no allocation) ----------------
__device__ float g_bufA[(size_t)NB * NV * 512];   // x2 bf16 plane (first half)
__device__ float g_bufB[(size_t)NB * NV * 512];   // t2 bf16 (first half); second half = dummy scratch
__device__ float g_s3a[NB * NV * 3];
__device__ float g_s3b[NB * NV * 3];
__device__ float g_s3c[NB * NV * 3];
__device__ float g_imgstage[NB * 512];
__device__ float g_imgterm[NB * 512];
__device__ __nv_bfloat16 g_W34T[512 * 512];       // W34 transposed [N,K] bf16
__device__ float g_W12c[3 * 512];
__device__ float g_W56[512 * 3];
__device__ float g_b1W2[512];
__device__ float g_b3W4[512];
__device__ float g_b5W6[3];
__device__ float g_s1[NV];
__device__ float g_s2[NV];
__device__ float g_dinv[NV];
__device__ float g_nrm[NNZ];
__device__ int   g_rowptr[NV + 1];
__device__ int   g_cols[NNZ];
__device__ int   g_counts[NV];
__device__ int   g_fill[NV];
__device__ float g_fch1[NB * 1024];
__device__ float g_fch2[NB * 1024];
__device__ float g_fcout[NB * 6144];

// ---------------- graph/CSR setup ----------------
__global__ void k_init() {
    int i = blockIdx.x * blockDim.x + threadIdx.x;
    if (i < NV) { g_counts[i] = 1; g_fill[i] = 0; }
}
__global__ void k_deg(const int* __restrict__ edge) {
    int e = blockIdx.x * blockDim.x + threadIdx.x;
    if (e < NEDGE) atomicAdd(&g_counts[edge[NEDGE + e]], 1);
}
__global__ void k_scan() {
    __shared__ int p[1024];
    int t = threadIdx.x;
    int c0 = g_counts[2 * t], c1 = g_counts[2 * t + 1];
    g_dinv[2 * t]     = rsqrtf((float)c0);
    g_dinv[2 * t + 1] = rsqrtf((float)c1);
    p[t] = c0 + c1;
    __syncthreads();
    for (int off = 1; off < 1024; off <<= 1) {
        int v = (t >= off) ? p[t - off] : 0;
        __syncthreads();
        p[t] += v;
        __syncthreads();
    }
    int base = p[t] - (c0 + c1);
    g_rowptr[2 * t] = base;
    g_rowptr[2 * t + 1] = base + c0;
    if (t == 1023) g_rowptr[2048] = p[1023];
}
__global__ void k_fill(const int* __restrict__ edge) {
    int i = blockIdx.x * blockDim.x + threadIdx.x;
    if (i < NEDGE) {
        int s = edge[i], d = edge[NEDGE + i];
        int pos = g_rowptr[d] + atomicAdd(&g_fill[d], 1);
        g_cols[pos] = s;
        g_nrm[pos] = g_dinv[s] * g_dinv[d];
    } else if (i < NNZ) {
        int v = i - NEDGE;
        int pos = g_rowptr[v] + atomicAdd(&g_fill[v], 1);
        g_cols[pos] = v;
        g_nrm[pos] = g_dinv[v] * g_dinv[v];
    }
}
__global__ void k_s1() {
    int v = blockIdx.x * blockDim.x + threadIdx.x;
    if (v >= NV) return;
    float s = 0.f;
    for (int j = g_rowptr[v]; j < g_rowptr[v + 1]; j++) s += g_nrm[j];
    g_s1[v] = s;
}
__global__ void k_s2() {
    int v = blockIdx.x * blockDim.x + threadIdx.x;
    if (v >= NV) return;
    float s = 0.f;
    for (int j = g_rowptr[v]; j < g_rowptr[v + 1]; j++) s += g_nrm[j] * g_s1[g_cols[j]];
    g_s2[v] = s;
}
__global__ void k_zero3a() {
    int i = blockIdx.x * blockDim.x + threadIdx.x;
    if (i < NB * NV * 3) g_s3a[i] = 0.f;
}

// ---------------- generic small matmul (imgstage/imgterm; L2-resident, proven fast) ----------------
__global__ void k_smallmm(const float* __restrict__ A, const float* __restrict__ Bw,
                          float* __restrict__ C, int M, int K, int N, int strideA) {
    int i = blockIdx.x * blockDim.x + threadIdx.x;
    if (i >= M * N) return;
    int m = i / N, o = i - m * N;
    float acc = 0.f;
    const float* a = A + (size_t)m * strideA;
    for (int k = 0; k < K; k++) acc += a[k] * Bw[(size_t)k * N + o];
    C[i] = acc;
}

// ---------------- fused tiny weight-prep ----------------
__global__ void k_prepsmall(const float* __restrict__ W1, const float* __restrict__ W2,
                            const float* __restrict__ b1, const float* __restrict__ b3,
                            const float* __restrict__ W4, const float* __restrict__ W5,
                            const float* __restrict__ W6, const float* __restrict__ b5) {
    int i = blockIdx.x * blockDim.x + threadIdx.x;
    if (i < 1536) {
        int m = i / 512, o = i - m * 512;
        float acc = 0.f;
        for (int k = 0; k < 512; k++) acc += W1[m * 512 + k] * W2[(size_t)k * 512 + o];
        g_W12c[i] = acc;
    } else if (i < 2048) {
        int o = i - 1536;
        float acc = 0.f;
        for (int k = 0; k < 512; k++) acc += b1[k] * W2[(size_t)k * 512 + o];
        g_b1W2[o] = acc;
    } else if (i < 2560) {
        int o = i - 2048;
        float acc = 0.f;
        for (int k = 0; k < 512; k++) acc += b3[k] * W4[(size_t)k * 512 + o];
        g_b3W4[o] = acc;
    } else if (i < 4096) {
        int j = i - 2560;
        int m = j / 3, o = j - m * 3;
        float acc = 0.f;
        for (int k = 0; k < 64; k++) acc += W5[m * 64 + k] * W6[k * 3 + o];
        g_W56[j] = acc;
    } else if (i < 4099) {
        int o = i - 4096;
        float acc = 0.f;
        for (int k = 0; k < 64; k++) acc += b5[k] * W6[k * 3 + o];
        g_b5W6[o] = acc;
    }
}

// ---------------- W34 = W3@W4, epilogue writes transposed bf16 directly ----------------
__global__ void __launch_bounds__(256) sgemm64T(const float* __restrict__ A,
                                                const float* __restrict__ Bw,
                                                int M, int N, int K) {
    __shared__ float As[16][64];
    __shared__ float Bs[16][68];
    int tid = threadIdx.x;
    int row0 = blockIdx.y * 64, col0 = blockIdx.x * 64;
    int aRow = tid >> 2, aCol = (tid & 3) * 4;
    int bRow = tid >> 4, bCol = (tid & 15) * 4;
    int tx = tid & 15, ty = tid >> 4;
    float acc[4][4];
#pragma unroll
    for (int i = 0; i < 4; i++)
#pragma unroll
        for (int j = 0; j < 4; j++) acc[i][j] = 0.f;
    for (int k0 = 0; k0 < K; k0 += 16) {
        float4 av = *(const float4*)&A[(size_t)(row0 + aRow) * K + k0 + aCol];
        float4 bv = *(const float4*)&Bw[(size_t)(k0 + bRow) * N + col0 + bCol];
        As[aCol + 0][aRow] = av.x;
        As[aCol + 1][aRow] = av.y;
        As[aCol + 2][aRow] = av.z;
        As[aCol + 3][aRow] = av.w;
        Bs[bRow][bCol + 0] = bv.x;
        Bs[bRow][bCol + 1] = bv.y;
        Bs[bRow][bCol + 2] = bv.z;
        Bs[bRow][bCol + 3] = bv.w;
        __syncthreads();
#pragma unroll
        for (int kk = 0; kk < 16; kk++) {
            float ar[4], br[4];
#pragma unroll
            for (int i = 0; i < 4; i++) ar[i] = As[kk][ty * 4 + i];
#pragma unroll
            for (int j = 0; j < 4; j++) br[j] = Bs[kk][tx * 4 + j];
#pragma unroll
            for (int i = 0; i < 4; i++)
#pragma unroll
                for (int j = 0; j < 4; j++) acc[i][j] = fmaf(ar[i], br[j], acc[i][j]);
        }
        __syncthreads();
    }
#pragma unroll
    for (int i = 0; i < 4; i++) {
        int krow = row0 + ty * 4 + i;
#pragma unroll
        for (int j = 0; j < 4; j++) {
            int ncol = col0 + tx * 4 + j;
            g_W34T[(size_t)ncol * 512 + krow] = __float2bfloat16(acc[i][j]);
        }
    }
}

// ---------------- aggregation, F=3 ----------------
__global__ void k_agg3(const float* __restrict__ in, float* __restrict__ out,
                       const float* __restrict__ biasA, const float* __restrict__ biasB,
                       int relu) {
    int i = blockIdx.x * blockDim.x + threadIdx.x;
    if (i >= NB * NV) return;
    int v = i & (NV - 1);
    int b = i >> 11;
    float a0 = 0.f, a1 = 0.f, a2 = 0.f;
    int beg = g_rowptr[v], end = g_rowptr[v + 1];
    const float* base = in + (size_t)b * NV * 3;
    for (int j = beg; j < end; j++) {
        int s = g_cols[j];
        float w = g_nrm[j];
        const float* p = base + s * 3;
        a0 = fmaf(w, p[0], a0);
        a1 = fmaf(w, p[1], a1);
        a2 = fmaf(w, p[2], a2);
    }
    if (biasA) {
        float s1v = g_s1[v];
        a0 += s1v * biasA[0] + biasB[0];
        a1 += s1v * biasA[1] + biasB[1];
        a2 += s1v * biasA[2] + biasB[2];
    }
    if (relu) { a0 = fmaxf(0.f, a0); a1 = fmaxf(0.f, a1); a2 = fmaxf(0.f, a2); }
    float* o = out + (size_t)i * 3;
    o[0] = a0; o[1] = a1; o[2] = a2;
}

// ---------------- x2 assembly -> bf16 plane (weights register-resident, loop over v) ----------------
__global__ void __launch_bounds__(128) k_x2(const float* __restrict__ b2,
                                            __nv_bfloat16* __restrict__ ahi) {
    int og = threadIdx.x;            // quad index 0..127
    int b  = blockIdx.x >> 4;        // batch
    int vc = blockIdx.x & 15;        // vertex chunk of 128
    float4 w0 = ((const float4*)g_W12c)[0 * 128 + og];
    float4 w1 = ((const float4*)g_W12c)[1 * 128 + og];
    float4 w2 = ((const float4*)g_W12c)[2 * 128 + og];
    float4 it = ((const float4*)g_imgterm)[b * 128 + og];
    float4 bw = ((const float4*)g_b1W2)[og];
    float4 bb = ((const float4*)b2)[og];
    const float* s3 = g_s3b + ((size_t)b * NV + vc * 128) * 3;
    ushort4* outp = (ushort4*)ahi + ((size_t)b * NV + vc * 128) * 128 + og;
#pragma unroll 4
    for (int k = 0; k < 128; k++) {
        int v = vc * 128 + k;
        float a0 = s3[k * 3 + 0], a1 = s3[k * 3 + 1], a2 = s3[k * 3 + 2];
        float s1v = g_s1[v], s2v = g_s2[v];
        float r[4];
        r[0] = fmaxf(0.f, a0 * w0.x + a1 * w1.x + a2 * w2.x + s2v * it.x + s1v * bw.x + bb.x);
        r[1] = fmaxf(0.f, a0 * w0.y + a1 * w1.y + a2 * w2.y + s2v * it.y + s1v * bw.y + bb.y);
        r[2] = fmaxf(0.f, a0 * w0.z + a1 * w1.z + a2 * w2.z + s2v * it.z + s1v * bw.z + bb.z);
        r[3] = fmaxf(0.f, a0 * w0.w + a1 * w1.w + a2 * w2.w + s2v * it.w + s1v * bw.w + bb.w);
        ushort4 hv;
        unsigned short* hp = &hv.x;
#pragma unroll
        for (int q = 0; q < 4; q++) {
            __nv_bfloat16 h = __float2bfloat16(r[q]);
            hp[q] = *(unsigned short*)&h;
        }
        outp[(size_t)k * 128] = hv;
    }
}

// ---------------- fused two-hop aggregation: t2 = A^2(x2), smem-resident ----------------
#define AG_STRIDE 48
#define AG_SMEM   (NV * AG_STRIDE)   // 98304
__global__ void __launch_bounds__(1024) k_agg2hop(const __nv_bfloat16* __restrict__ x2,
                                                  __nv_bfloat16* __restrict__ t2) {
    extern __shared__ char sm[];
    int f0 = blockIdx.x * 16;
    int b  = blockIdx.y;
    int t  = threadIdx.x;
    const __nv_bfloat16* xb = x2 + (size_t)b * NV * 512 + f0;
    __nv_bfloat16* ob = t2 + (size_t)b * NV * 512 + f0;
#pragma unroll
    for (int r = 0; r < 2; r++) {
        int v = t + r * 1024;
        const uint4* src = (const uint4*)(xb + (size_t)v * 512);
        uint4* d = (uint4*)(sm + v * AG_STRIDE);
        d[0] = src[0]; d[1] = src[1];
    }
    __syncthreads();
    uint4 keep[2][2];
#pragma unroll
    for (int r = 0; r < 2; r++) {
        int v = t + r * 1024;
        float acc[16];
#pragma unroll
        for (int q = 0; q < 16; q++) acc[q] = 0.f;
        int beg = g_rowptr[v], end = g_rowptr[v + 1];
        for (int j = beg; j < end; j++) {
            int s = g_cols[j];
            float w = g_nrm[j];
            uint4 q0 = *(const uint4*)(sm + s * AG_STRIDE);
            uint4 q1 = *(const uint4*)(sm + s * AG_STRIDE + 16);
            const __nv_bfloat162* h0 = (const __nv_bfloat162*)&q0;
            const __nv_bfloat162* h1 = (const __nv_bfloat162*)&q1;
#pragma unroll
            for (int q = 0; q < 4; q++) {
                float2 f = __bfloat1622float2(h0[q]);
                acc[2 * q]     = fmaf(w, f.x, acc[2 * q]);
                acc[2 * q + 1] = fmaf(w, f.y, acc[2 * q + 1]);
                float2 g = __bfloat1622float2(h1[q]);
                acc[8 + 2 * q]     = fmaf(w, g.x, acc[8 + 2 * q]);
                acc[8 + 2 * q + 1] = fmaf(w, g.y, acc[8 + 2 * q + 1]);
            }
        }
        __nv_bfloat162* kp = (__nv_bfloat162*)keep[r];
#pragma unroll
        for (int q = 0; q < 8; q++) kp[q] = __floats2bfloat162_rn(acc[2 * q], acc[2 * q + 1]);
    }
    __syncthreads();
#pragma unroll
    for (int r = 0; r < 2; r++) {
        int v = t + r * 1024;
        uint4* d = (uint4*)(sm + v * AG_STRIDE);
        d[0] = keep[r][0]; d[1] = keep[r][1];
    }
    __syncthreads();
#pragma unroll
    for (int r = 0; r < 2; r++) {
        int v = t + r * 1024;
        float acc[16];
#pragma unroll
        for (int q = 0; q < 16; q++) acc[q] = 0.f;
        int beg = g_rowptr[v], end = g_rowptr[v + 1];
        for (int j = beg; j < end; j++) {
            int s = g_cols[j];
            float w = g_nrm[j];
            uint4 q0 = *(const uint4*)(sm + s * AG_STRIDE);
            uint4 q1 = *(const uint4*)(sm + s * AG_STRIDE + 16);
            const __nv_bfloat162* h0 = (const __nv_bfloat162*)&q0;
            const __nv_bfloat162* h1 = (const __nv_bfloat162*)&q1;
#pragma unroll
            for (int q = 0; q < 4; q++) {
                float2 f = __bfloat1622float2(h0[q]);
                acc[2 * q]     = fmaf(w, f.x, acc[2 * q]);
                acc[2 * q + 1] = fmaf(w, f.y, acc[2 * q + 1]);
                float2 g = __bfloat1622float2(h1[q]);
                acc[8 + 2 * q]     = fmaf(w, g.x, acc[8 + 2 * q]);
                acc[8 + 2 * q + 1] = fmaf(w, g.y, acc[8 + 2 * q + 1]);
            }
        }
        uint4 pk[2];
        __nv_bfloat162* pp = (__nv_bfloat162*)pk;
#pragma unroll
        for (int q = 0; q < 8; q++) pp[q] = __floats2bfloat162_rn(acc[2 * q], acc[2 * q + 1]);
        uint4* d = (uint4*)(ob + (size_t)v * 512);
        d[0] = pk[0]; d[1] = pk[1];
    }
}

// ---------------- mma.sync bf16 GEMM + fused bias/relu/W56-projection epilogue ----------------
// outacc: atomicAdd target ([M,3]); real run -> g_s3a, diagnostic dummy -> dead scratch.
__global__ void __launch_bounds__(256, 2) gemm_mma(
    const uint4* __restrict__ Ah, const uint4* __restrict__ Bh,
    const float* __restrict__ b4, float* __restrict__ outacc) {
    extern __shared__ char smem[];
    uint32_t sb = smem_to_u32(smem);
    int tid = threadIdx.x, lane = tid & 31, wid = tid >> 5;
    int wr = wid & 3, wc = wid >> 2;
    int row0 = blockIdx.y << 7, col0 = blockIdx.x << 7;

    auto load_chunk = [&](int kc, int stage) {
        uint32_t st = sb + stage * 16384;
#pragma unroll
        for (int i = tid; i < 512; i += 256) {
            int r = i >> 2, c = i & 3;
            uint32_t soff = SWZ(r * 64 + c * 16);
            size_t ga = (size_t)(row0 + r) * 64 + kc * 4 + c;
            size_t gb = (size_t)(col0 + r) * 64 + kc * 4 + c;
            CP_ASYNC16(st + soff,        (const void*)(Ah + ga));
            CP_ASYNC16(st + 8192 + soff, (const void*)(Bh + gb));
        }
    };

    load_chunk(0, 0); CP_COMMIT;
    load_chunk(1, 1); CP_COMMIT;
    load_chunk(2, 2); CP_COMMIT;

    float acc[2][8][4];
#pragma unroll
    for (int mt = 0; mt < 2; mt++)
#pragma unroll
        for (int nt = 0; nt < 8; nt++)
#pragma unroll
            for (int q = 0; q < 4; q++) acc[mt][nt][q] = 0.f;

    for (int kc = 0; kc < 16; kc++) {
        CP_WAIT_GROUP(2);
        __syncthreads();
        if (kc + 3 < 16) load_chunk(kc + 3, (kc + 3) & 3);
        CP_COMMIT;
        uint32_t base = sb + (kc & 3) * 16384;
#pragma unroll
        for (int ks = 0; ks < 2; ks++) {
            uint32_t ah[2][4];
#pragma unroll
            for (int mt = 0; mt < 2; mt++) {
                int r = wr * 32 + mt * 16 + (lane & 15);
                uint32_t off = SWZ(r * 64 + ks * 32 + ((lane >> 4) << 4));
                LDM4(ah[mt], base + off);
            }
#pragma unroll
            for (int nt2 = 0; nt2 < 4; nt2++) {
                int nrow = wc * 64 + nt2 * 16 + (lane & 7) + ((lane >> 4) << 3);
                uint32_t off = SWZ(nrow * 64 + ks * 32 + (((lane >> 3) & 1) << 4));
                uint32_t bhf[4];
                LDM4(bhf, base + 8192 + off);
#pragma unroll
                for (int h = 0; h < 2; h++) {
                    uint32_t bh2[2] = { bhf[2 * h], bhf[2 * h + 1] };
                    int nt = 2 * nt2 + h;
#pragma unroll
                    for (int mt = 0; mt < 2; mt++)
                        MMA16816(acc[mt][nt], ah[mt], bh2);
                }
            }
        }
    }

    // epilogue: bias + relu + W56 projection, atomicAdd into outacc
    float p[4][3];
#pragma unroll
    for (int r = 0; r < 4; r++) { p[r][0] = 0.f; p[r][1] = 0.f; p[r][2] = 0.f; }
    int R = row0 + wr * 32 + (lane >> 2);
    float s1r[4];
#pragma unroll
    for (int r = 0; r < 4; r++)
        s1r[r] = g_s1[(R + ((r >> 1) << 4) + ((r & 1) << 3)) & (NV - 1)];
#pragma unroll
    for (int mt = 0; mt < 2; mt++) {
#pragma unroll
        for (int nt = 0; nt < 8; nt++) {
            int c = col0 + wc * 64 + nt * 8 + ((lane & 3) << 1);
            float bw0 = g_b3W4[c],     bc0 = b4[c];
            float bw1 = g_b3W4[c + 1], bc1 = b4[c + 1];
            float wa0 = g_W56[c * 3 + 0], wa1 = g_W56[c * 3 + 1], wa2 = g_W56[c * 3 + 2];
            float wb0 = g_W56[(c + 1) * 3 + 0], wb1 = g_W56[(c + 1) * 3 + 1], wb2 = g_W56[(c + 1) * 3 + 2];
            int ra = mt * 2, rb = mt * 2 + 1;
            float u;
            u = fmaxf(0.f, acc[mt][nt][0] + s1r[ra] * bw0 + bc0);
            p[ra][0] = fmaf(u, wa0, p[ra][0]); p[ra][1] = fmaf(u, wa1, p[ra][1]); p[ra][2] = fmaf(u, wa2, p[ra][2]);
            u = fmaxf(0.f, acc[mt][nt][1] + s1r[ra] * bw1 + bc1);
            p[ra][0] = fmaf(u, wb0, p[ra][0]); p[ra][1] = fmaf(u, wb1, p[ra][1]); p[ra][2] = fmaf(u, wb2, p[ra][2]);
            u = fmaxf(0.f, acc[mt][nt][2] + s1r[rb] * bw0 + bc0);
            p[rb][0] = fmaf(u, wa0, p[rb][0]); p[rb][1] = fmaf(u, wa1, p[rb][1]); p[rb][2] = fmaf(u, wa2, p[rb][2]);
            u = fmaxf(0.f, acc[mt][nt][3] + s1r[rb] * bw1 + bc1);
            p[rb][0] = fmaf(u, wb0, p[rb][0]); p[rb][1] = fmaf(u, wb1, p[rb][1]); p[rb][2] = fmaf(u, wb2, p[rb][2]);
        }
    }
#pragma unroll
    for (int r = 0; r < 4; r++)
#pragma unroll
        for (int k = 0; k < 3; k++) {
            p[r][k] += __shfl_xor_sync(0xffffffffu, p[r][k], 1);
            p[r][k] += __shfl_xor_sync(0xffffffffu, p[r][k], 2);
        }
    if ((lane & 3) == 0) {
#pragma unroll
        for (int r = 0; r < 4; r++) {
            int m = R + ((r >> 1) << 4) + ((r & 1) << 3);
            atomicAdd(&outacc[(size_t)m * 3 + 0], p[r][0]);
            atomicAdd(&outacc[(size_t)m * 3 + 1], p[r][1]);
            atomicAdd(&outacc[(size_t)m * 3 + 2], p[r][2]);
        }
    }
}

// ---------------- FC head ----------------
__global__ void k_cinit3(const float* __restrict__ fcb1, const float* __restrict__ fcb2,
                         const float* __restrict__ fcb3) {
    int i = blockIdx.x * blockDim.x + threadIdx.x;
    if (i < 32 * 1024) {
        g_fch1[i] = fcb1[i & 1023];
        g_fch2[i] = fcb2[i & 1023];
    }
    if (i < 32 * 6144) g_fcout[i] = fcb3[i % 6144];
}

__global__ void __launch_bounds__(256) fcgemm_sk(const float* __restrict__ A,
                                                 const float* __restrict__ W,
                                                 float* __restrict__ C,
                                                 int K, int N, int Kc) {
    __shared__ float As[32][33];
    int tid = threadIdx.x;
    int o = blockIdx.x * 64 + (tid & 63);
    int bg = (tid >> 6) * 8;
    int k0base = blockIdx.y * Kc;
    float acc[8];
#pragma unroll
    for (int r = 0; r < 8; r++) acc[r] = 0.f;
    for (int k0 = k0base; k0 < k0base + Kc; k0 += 32) {
#pragma unroll
        for (int l = 0; l < 4; l++) {
            int idx = tid + 256 * l;
            int r = idx >> 5, kk = idx & 31;
            As[r][kk] = A[(size_t)r * K + k0 + kk];
        }
        __syncthreads();
#pragma unroll 8
        for (int kk = 0; kk < 32; kk++) {
            float w = W[(size_t)(k0 + kk) * N + o];
#pragma unroll
            for (int r = 0; r < 8; r++) acc[r] = fmaf(As[bg + r][kk], w, acc[r]);
        }
        __syncthreads();
    }
#pragma unroll
    for (int r = 0; r < 8; r++) atomicAdd(&C[(size_t)(bg + r) * N + o], acc[r]);
}

// ---------------- final: out = verts + 0.1*tanh(fcout) ----------------
__global__ void k_final(const float* __restrict__ verts, float* __restrict__ out) {
    int i = blockIdx.x * blockDim.x + threadIdx.x;
    if (i >= NB * NV * 3) return;
    out[i] = verts[i] + 0.1f * tanhf(g_fcout[i]);
}

// ---------------- host launcher ----------------
extern "C" void kernel_launch(void* const* d_in, const int* in_sizes, int n_in,
                              void* d_out, int out_size) {
    const float* verts = (const float*)d_in[0];
    const float* img   = (const float*)d_in[1];
    const int*   edge  = (const int*)d_in[2];
    const float* W1 = (const float*)d_in[3];   const float* b1 = (const float*)d_in[4];
    const float* W2 = (const float*)d_in[5];   const float* b2 = (const float*)d_in[6];
    const float* W3 = (const float*)d_in[7];   const float* b3 = (const float*)d_in[8];
    const float* W4 = (const float*)d_in[9];   const float* b4 = (const float*)d_in[10];
    const float* W5 = (const float*)d_in[11];  const float* b5 = (const float*)d_in[12];
    const float* W6 = (const float*)d_in[13];  const float* b6 = (const float*)d_in[14];
    const float* fcW1 = (const float*)d_in[15]; const float* fcb1 = (const float*)d_in[16];
    const float* fcW2 = (const float*)d_in[17]; const float* fcb2 = (const float*)d_in[18];
    const float* fcW3 = (const float*)d_in[19]; const float* fcb3 = (const float*)d_in[20];
    float* out = (float*)d_out;

    float *bufA, *bufB, *s3a, *s3b, *s3c, *imgstage, *imgterm, *b5W6;
    float *fch1, *fch2, *fcout;
    __nv_bfloat16 *w34t;
    cudaGetSymbolAddress((void**)&bufA, g_bufA);
    cudaGetSymbolAddress((void**)&bufB, g_bufB);
    cudaGetSymbolAddress((void**)&s3a, g_s3a);
    cudaGetSymbolAddress((void**)&s3b, g_s3b);
    cudaGetSymbolAddress((void**)&s3c, g_s3c);
    cudaGetSymbolAddress((void**)&imgstage, g_imgstage);
    cudaGetSymbolAddress((void**)&imgterm, g_imgterm);
    cudaGetSymbolAddress((void**)&w34t, g_W34T);
    cudaGetSymbolAddress((void**)&b5W6, g_b5W6);
    cudaGetSymbolAddress((void**)&fch1, g_fch1);
    cudaGetSymbolAddress((void**)&fch2, g_fch2);
    cudaGetSymbolAddress((void**)&fcout, g_fcout);

    __nv_bfloat16* x2h = (__nv_bfloat16*)bufA;                       // first half of bufA
    __nv_bfloat16* t2h = (__nv_bfloat16*)bufB;                       // first half of bufB
    float* scratch = bufB + (size_t)NB * NV * 256;                   // second half of bufB (dead)

    cudaFuncSetAttribute(gemm_mma, cudaFuncAttributeMaxDynamicSharedMemorySize, 65536);
    cudaFuncSetAttribute(k_agg2hop, cudaFuncAttributeMaxDynamicSharedMemorySize, AG_SMEM);

    // --- graph/CSR + norm ---
    k_init<<<8, 256>>>();                                            // #1
    k_deg<<<48, 256>>>(edge);                                        // #2
    k_scan<<<1, 1024>>>();                                           // #3
    // DIAGNOSTIC: one-wave dummy GEMM at launch #4 (ncu profiles this slot).
    // Reads stale t2h/w34t (deterministic per replay), writes to dead scratch.
    gemm_mma<<<dim3(4, 37), 256, 65536>>>((const uint4*)t2h, (const uint4*)w34t, b4, scratch);  // #4
    k_fill<<<56, 256>>>(edge);
    k_s1<<<8, 256>>>();
    k_s2<<<8, 256>>>();
    k_zero3a<<<768, 256>>>();

    // --- weight precompute ---
    k_prepsmall<<<17, 256>>>(W1, W2, b1, b3, W4, W5, W6, b5);
    k_smallmm<<<64, 256>>>(img, W1 + 3 * 512, imgstage, NB, 512, 512, 512);
    k_smallmm<<<64, 256>>>(imgstage, W2, imgterm, NB, 512, 512, 512);
    sgemm64T<<<dim3(8, 8), 256>>>(W3, W4, 512, 512, 512);

    // --- layers 1+2 fused ---
    k_agg3<<<256, 256>>>(verts, s3c, NULL, NULL, 0);
    k_agg3<<<256, 256>>>(s3c, s3b, NULL, NULL, 0);
    k_x2<<<512, 128>>>(b2, x2h);

    // --- layers 3+4: t2 = A^2(x2), then GEMM w/ proj epilogue -> s3a ---
    k_agg2hop<<<dim3(32, 32), 1024, AG_SMEM>>>(x2h, t2h);
    gemm_mma<<<dim3(4, 512), 256, 65536>>>((const uint4*)t2h, (const uint4*)w34t, b4, s3a);

    // --- layers 5+6 remainder: A^2 on F=3 + bias + relu ---
    k_agg3<<<256, 256>>>(s3a, s3b, NULL, NULL, 0);
    k_agg3<<<256, 256>>>(s3b, s3c, b5W6, b6, 1);

    // --- FC head ---
    k_cinit3<<<768, 256>>>(fcb1, fcb2, fcb3);
    fcgemm_sk<<<dim3(16, 24), 256>>>(s3c, fcW1, fch1, 6144, 1024, 256);
    fcgemm_sk<<<dim3(16, 8), 256>>>(fch1, fcW2, fch2, 1024, 1024, 128);
    fcgemm_sk<<<dim3(96, 4), 256>>>(fch2, fcW3, fcout, 1024, 6144, 256);

    // --- output ---
    k_final<<<768, 256>>>(verts, out);
}

// round 13
// speedup vs baseline: 1.1250x; 1.0617x over previous
#include <cuda_runtime.h>
#include <cuda_bf16.h>
#include <cstdint>
#include <math.h>

#define NB 32
#define NV 2048
#define NEDGE 12288
#define NNZ (NEDGE + NV)   // 14336 (edges + self loops)

// ================= helpers (plain sm_103-safe) =================
__device__ __forceinline__ uint32_t smem_to_u32(const void* smem_ptr) {
    uint32_t addr;
    asm("{ .reg .u64 tmp; cvta.to.shared.u64 tmp, %1; cvt.u32.u64 %0, tmp; }"
        : "=r"(addr) : "l"(smem_ptr));
    return addr;
}
#define SWZ(o) ((o) ^ (((o) >> 3) & 0x70))
#define CP_ASYNC16(dst, src) \
    asm volatile("cp.async.cg.shared.global [%0], [%1], 16;" :: "r"(dst), "l"(src))
#define CP_COMMIT asm volatile("cp.async.commit_group;" ::: "memory")
#define CP_WAIT_GROUP(n) asm volatile("cp.async.wait_group %0;" :: "n"(n) : "memory")
#define LDM4(r, addr) \
    asm volatile("ldmatrix.sync.aligned.m8n8.x4.shared.b16 {%0,%1,%2,%3}, [%4];" \
        : "=r"((r)[0]), "=r"((r)[1]), "=r"((r)[2]), "=r"((r)[3]) : "r"(addr))
#define MMA16816(d, a, b) \
    asm volatile("mma.sync.aligned.m16n8k16.row.col.f32.bf16.bf16.f32 " \
        "{%0,%1,%2,%3}, {%4,%5,%6,%7}, {%8,%9}, {%0,%1,%2,%3};" \
        : "+f"((d)[0]), "+f"((d)[1]), "+f"((d)[2]), "+f"((d)[3]) \
        : "r"((a)[0]), "r"((a)[1]), "r"((a)[2]), "r"((a)[3]), "r"((b)[0]), "r"((b)[1]))

// ---------------- scratch (device globals; no allocation) ----------------
__device__ float g_bufA[(size_t)NB * NV * 512];   // x2 bf16 plane
__device__ float g_bufB[(size_t)NB * NV * 512];   // t2 bf16
__device__ float g_s3a[NB * NV * 3];
__device__ float g_s3b[NB * NV * 3];
__device__ float g_s3c[NB * NV * 3];
__device__ float g_imgstage[NB * 512];
__device__ float g_imgterm[NB * 512];
__device__ __nv_bfloat16 g_W34T[512 * 512];       // W34 transposed [N,K] bf16
__device__ float g_W12c[3 * 512];
__device__ float g_W56[512 * 3];
__device__ float g_b1W2[512];
__device__ float g_b3W4[512];
__device__ float g_b5W6[3];
__device__ float g_s1[NV];
__device__ float g_s2[NV];
__device__ float g_dinv[NV];
__device__ float g_nrm[NNZ];
__device__ int   g_rowptr[NV + 1];
__device__ int   g_cols[NNZ];
__device__ int   g_counts[NV];
__device__ int   g_fill[NV];
__device__ float g_fch1[NB * 1024];
__device__ float g_fch2[NB * 1024];
__device__ float g_fcout[NB * 6144];

// ---------------- graph/CSR setup ----------------
__global__ void k_init() {
    int i = blockIdx.x * blockDim.x + threadIdx.x;
    if (i < NV) { g_counts[i] = 1; g_fill[i] = 0; }
}
__global__ void k_deg(const int* __restrict__ edge) {
    int e = blockIdx.x * blockDim.x + threadIdx.x;
    if (e < NEDGE) atomicAdd(&g_counts[edge[NEDGE + e]], 1);
}
__global__ void k_scan() {
    __shared__ int p[1024];
    int t = threadIdx.x;
    int c0 = g_counts[2 * t], c1 = g_counts[2 * t + 1];
    g_dinv[2 * t]     = rsqrtf((float)c0);
    g_dinv[2 * t + 1] = rsqrtf((float)c1);
    p[t] = c0 + c1;
    __syncthreads();
    for (int off = 1; off < 1024; off <<= 1) {
        int v = (t >= off) ? p[t - off] : 0;
        __syncthreads();
        p[t] += v;
        __syncthreads();
    }
    int base = p[t] - (c0 + c1);
    g_rowptr[2 * t] = base;
    g_rowptr[2 * t + 1] = base + c0;
    if (t == 1023) g_rowptr[2048] = p[1023];
}
__global__ void k_fill(const int* __restrict__ edge) {
    int i = blockIdx.x * blockDim.x + threadIdx.x;
    if (i < NEDGE) {
        int s = edge[i], d = edge[NEDGE + i];
        int pos = g_rowptr[d] + atomicAdd(&g_fill[d], 1);
        g_cols[pos] = s;
        g_nrm[pos] = g_dinv[s] * g_dinv[d];
    } else if (i < NNZ) {
        int v = i - NEDGE;
        int pos = g_rowptr[v] + atomicAdd(&g_fill[v], 1);
        g_cols[pos] = v;
        g_nrm[pos] = g_dinv[v] * g_dinv[v];
    }
}
__global__ void k_s1() {
    int v = blockIdx.x * blockDim.x + threadIdx.x;
    if (v >= NV) return;
    float s = 0.f;
    for (int j = g_rowptr[v]; j < g_rowptr[v + 1]; j++) s += g_nrm[j];
    g_s1[v] = s;
}
__global__ void k_s2() {
    int v = blockIdx.x * blockDim.x + threadIdx.x;
    if (v >= NV) return;
    float s = 0.f;
    for (int j = g_rowptr[v]; j < g_rowptr[v + 1]; j++) s += g_nrm[j] * g_s1[g_cols[j]];
    g_s2[v] = s;
}
__global__ void k_zero3a() {
    int i = blockIdx.x * blockDim.x + threadIdx.x;
    if (i < NB * NV * 3) g_s3a[i] = 0.f;
}

// ---------------- generic small matmul (imgstage/imgterm; L2-resident) ----------------
__global__ void k_smallmm(const float* __restrict__ A, const float* __restrict__ Bw,
                          float* __restrict__ C, int M, int K, int N, int strideA) {
    int i = blockIdx.x * blockDim.x + threadIdx.x;
    if (i >= M * N) return;
    int m = i / N, o = i - m * N;
    float acc = 0.f;
    const float* a = A + (size_t)m * strideA;
    for (int k = 0; k < K; k++) acc += a[k] * Bw[(size_t)k * N + o];
    C[i] = acc;
}

// ---------------- fused tiny weight-prep ----------------
__global__ void k_prepsmall(const float* __restrict__ W1, const float* __restrict__ W2,
                            const float* __restrict__ b1, const float* __restrict__ b3,
                            const float* __restrict__ W4, const float* __restrict__ W5,
                            const float* __restrict__ W6, const float* __restrict__ b5) {
    int i = blockIdx.x * blockDim.x + threadIdx.x;
    if (i < 1536) {
        int m = i / 512, o = i - m * 512;
        float acc = 0.f;
        for (int k = 0; k < 512; k++) acc += W1[m * 512 + k] * W2[(size_t)k * 512 + o];
        g_W12c[i] = acc;
    } else if (i < 2048) {
        int o = i - 1536;
        float acc = 0.f;
        for (int k = 0; k < 512; k++) acc += b1[k] * W2[(size_t)k * 512 + o];
        g_b1W2[o] = acc;
    } else if (i < 2560) {
        int o = i - 2048;
        float acc = 0.f;
        for (int k = 0; k < 512; k++) acc += b3[k] * W4[(size_t)k * 512 + o];
        g_b3W4[o] = acc;
    } else if (i < 4096) {
        int j = i - 2560;
        int m = j / 3, o = j - m * 3;
        float acc = 0.f;
        for (int k = 0; k < 64; k++) acc += W5[m * 64 + k] * W6[k * 3 + o];
        g_W56[j] = acc;
    } else if (i < 4099) {
        int o = i - 4096;
        float acc = 0.f;
        for (int k = 0; k < 64; k++) acc += b5[k] * W6[k * 3 + o];
        g_b5W6[o] = acc;
    }
}

// ---------------- W34 = W3@W4, epilogue writes transposed bf16 directly ----------------
__global__ void __launch_bounds__(256) sgemm64T(const float* __restrict__ A,
                                                const float* __restrict__ Bw,
                                                int M, int N, int K) {
    __shared__ float As[16][64];
    __shared__ float Bs[16][68];
    int tid = threadIdx.x;
    int row0 = blockIdx.y * 64, col0 = blockIdx.x * 64;
    int aRow = tid >> 2, aCol = (tid & 3) * 4;
    int bRow = tid >> 4, bCol = (tid & 15) * 4;
    int tx = tid & 15, ty = tid >> 4;
    float acc[4][4];
#pragma unroll
    for (int i = 0; i < 4; i++)
#pragma unroll
        for (int j = 0; j < 4; j++) acc[i][j] = 0.f;
    for (int k0 = 0; k0 < K; k0 += 16) {
        float4 av = *(const float4*)&A[(size_t)(row0 + aRow) * K + k0 + aCol];
        float4 bv = *(const float4*)&Bw[(size_t)(k0 + bRow) * N + col0 + bCol];
        As[aCol + 0][aRow] = av.x;
        As[aCol + 1][aRow] = av.y;
        As[aCol + 2][aRow] = av.z;
        As[aCol + 3][aRow] = av.w;
        Bs[bRow][bCol + 0] = bv.x;
        Bs[bRow][bCol + 1] = bv.y;
        Bs[bRow][bCol + 2] = bv.z;
        Bs[bRow][bCol + 3] = bv.w;
        __syncthreads();
#pragma unroll
        for (int kk = 0; kk < 16; kk++) {
            float ar[4], br[4];
#pragma unroll
            for (int i = 0; i < 4; i++) ar[i] = As[kk][ty * 4 + i];
#pragma unroll
            for (int j = 0; j < 4; j++) br[j] = Bs[kk][tx * 4 + j];
#pragma unroll
            for (int i = 0; i < 4; i++)
#pragma unroll
                for (int j = 0; j < 4; j++) acc[i][j] = fmaf(ar[i], br[j], acc[i][j]);
        }
        __syncthreads();
    }
#pragma unroll
    for (int i = 0; i < 4; i++) {
        int krow = row0 + ty * 4 + i;
#pragma unroll
        for (int j = 0; j < 4; j++) {
            int ncol = col0 + tx * 4 + j;
            g_W34T[(size_t)ncol * 512 + krow] = __float2bfloat16(acc[i][j]);
        }
    }
}

// ---------------- aggregation, F=3 ----------------
__global__ void k_agg3(const float* __restrict__ in, float* __restrict__ out,
                       const float* __restrict__ biasA, const float* __restrict__ biasB,
                       int relu) {
    int i = blockIdx.x * blockDim.x + threadIdx.x;
    if (i >= NB * NV) return;
    int v = i & (NV - 1);
    int b = i >> 11;
    float a0 = 0.f, a1 = 0.f, a2 = 0.f;
    int beg = g_rowptr[v], end = g_rowptr[v + 1];
    const float* base = in + (size_t)b * NV * 3;
    for (int j = beg; j < end; j++) {
        int s = g_cols[j];
        float w = g_nrm[j];
        const float* p = base + s * 3;
        a0 = fmaf(w, p[0], a0);
        a1 = fmaf(w, p[1], a1);
        a2 = fmaf(w, p[2], a2);
    }
    if (biasA) {
        float s1v = g_s1[v];
        a0 += s1v * biasA[0] + biasB[0];
        a1 += s1v * biasA[1] + biasB[1];
        a2 += s1v * biasA[2] + biasB[2];
    }
    if (relu) { a0 = fmaxf(0.f, a0); a1 = fmaxf(0.f, a1); a2 = fmaxf(0.f, a2); }
    float* o = out + (size_t)i * 3;
    o[0] = a0; o[1] = a1; o[2] = a2;
}

// ---------------- x2 assembly -> bf16 plane (weights register-resident) ----------------
__global__ void __launch_bounds__(128) k_x2(const float* __restrict__ b2,
                                            __nv_bfloat16* __restrict__ ahi) {
    int og = threadIdx.x;            // quad index 0..127
    int b  = blockIdx.x >> 4;        // batch
    int vc = blockIdx.x & 15;        // vertex chunk of 128
    float4 w0 = ((const float4*)g_W12c)[0 * 128 + og];
    float4 w1 = ((const float4*)g_W12c)[1 * 128 + og];
    float4 w2 = ((const float4*)g_W12c)[2 * 128 + og];
    float4 it = ((const float4*)g_imgterm)[b * 128 + og];
    float4 bw = ((const float4*)g_b1W2)[og];
    float4 bb = ((const float4*)b2)[og];
    const float* s3 = g_s3b + ((size_t)b * NV + vc * 128) * 3;
    ushort4* outp = (ushort4*)ahi + ((size_t)b * NV + vc * 128) * 128 + og;
#pragma unroll 4
    for (int k = 0; k < 128; k++) {
        int v = vc * 128 + k;
        float a0 = s3[k * 3 + 0], a1 = s3[k * 3 + 1], a2 = s3[k * 3 + 2];
        float s1v = g_s1[v], s2v = g_s2[v];
        float r[4];
        r[0] = fmaxf(0.f, a0 * w0.x + a1 * w1.x + a2 * w2.x + s2v * it.x + s1v * bw.x + bb.x);
        r[1] = fmaxf(0.f, a0 * w0.y + a1 * w1.y + a2 * w2.y + s2v * it.y + s1v * bw.y + bb.y);
        r[2] = fmaxf(0.f, a0 * w0.z + a1 * w1.z + a2 * w2.z + s2v * it.z + s1v * bw.z + bb.z);
        r[3] = fmaxf(0.f, a0 * w0.w + a1 * w1.w + a2 * w2.w + s2v * it.w + s1v * bw.w + bb.w);
        ushort4 hv;
        unsigned short* hp = &hv.x;
#pragma unroll
        for (int q = 0; q < 4; q++) {
            __nv_bfloat16 h = __float2bfloat16(r[q]);
            hp[q] = *(unsigned short*)&h;
        }
        outp[(size_t)k * 128] = hv;
    }
}

// ---------------- fused two-hop aggregation: t2 = A^2(x2), smem-resident ----------------
#define AG_STRIDE 48
#define AG_SMEM   (NV * AG_STRIDE)   // 98304
__global__ void __launch_bounds__(1024) k_agg2hop(const __nv_bfloat16* __restrict__ x2,
                                                  __nv_bfloat16* __restrict__ t2) {
    extern __shared__ char sm[];
    int f0 = blockIdx.x * 16;
    int b  = blockIdx.y;
    int t  = threadIdx.x;
    const __nv_bfloat16* xb = x2 + (size_t)b * NV * 512 + f0;
    __nv_bfloat16* ob = t2 + (size_t)b * NV * 512 + f0;
#pragma unroll
    for (int r = 0; r < 2; r++) {
        int v = t + r * 1024;
        const uint4* src = (const uint4*)(xb + (size_t)v * 512);
        uint4* d = (uint4*)(sm + v * AG_STRIDE);
        d[0] = src[0]; d[1] = src[1];
    }
    __syncthreads();
    uint4 keep[2][2];
#pragma unroll
    for (int r = 0; r < 2; r++) {
        int v = t + r * 1024;
        float acc[16];
#pragma unroll
        for (int q = 0; q < 16; q++) acc[q] = 0.f;
        int beg = g_rowptr[v], end = g_rowptr[v + 1];
        for (int j = beg; j < end; j++) {
            int s = g_cols[j];
            float w = g_nrm[j];
            uint4 q0 = *(const uint4*)(sm + s * AG_STRIDE);
            uint4 q1 = *(const uint4*)(sm + s * AG_STRIDE + 16);
            const __nv_bfloat162* h0 = (const __nv_bfloat162*)&q0;
            const __nv_bfloat162* h1 = (const __nv_bfloat162*)&q1;
#pragma unroll
            for (int q = 0; q < 4; q++) {
                float2 f = __bfloat1622float2(h0[q]);
                acc[2 * q]     = fmaf(w, f.x, acc[2 * q]);
                acc[2 * q + 1] = fmaf(w, f.y, acc[2 * q + 1]);
                float2 g = __bfloat1622float2(h1[q]);
                acc[8 + 2 * q]     = fmaf(w, g.x, acc[8 + 2 * q]);
                acc[8 + 2 * q + 1] = fmaf(w, g.y, acc[8 + 2 * q + 1]);
            }
        }
        __nv_bfloat162* kp = (__nv_bfloat162*)keep[r];
#pragma unroll
        for (int q = 0; q < 8; q++) kp[q] = __floats2bfloat162_rn(acc[2 * q], acc[2 * q + 1]);
    }
    __syncthreads();
#pragma unroll
    for (int r = 0; r < 2; r++) {
        int v = t + r * 1024;
        uint4* d = (uint4*)(sm + v * AG_STRIDE);
        d[0] = keep[r][0]; d[1] = keep[r][1];
    }
    __syncthreads();
#pragma unroll
    for (int r = 0; r < 2; r++) {
        int v = t + r * 1024;
        float acc[16];
#pragma unroll
        for (int q = 0; q < 16; q++) acc[q] = 0.f;
        int beg = g_rowptr[v], end = g_rowptr[v + 1];
        for (int j = beg; j < end; j++) {
            int s = g_cols[j];
            float w = g_nrm[j];
            uint4 q0 = *(const uint4*)(sm + s * AG_STRIDE);
            uint4 q1 = *(const uint4*)(sm + s * AG_STRIDE + 16);
            const __nv_bfloat162* h0 = (const __nv_bfloat162*)&q0;
            const __nv_bfloat162* h1 = (const __nv_bfloat162*)&q1;
#pragma unroll
            for (int q = 0; q < 4; q++) {
                float2 f = __bfloat1622float2(h0[q]);
                acc[2 * q]     = fmaf(w, f.x, acc[2 * q]);
                acc[2 * q + 1] = fmaf(w, f.y, acc[2 * q + 1]);
                float2 g = __bfloat1622float2(h1[q]);
                acc[8 + 2 * q]     = fmaf(w, g.x, acc[8 + 2 * q]);
                acc[8 + 2 * q + 1] = fmaf(w, g.y, acc[8 + 2 * q + 1]);
            }
        }
        uint4 pk[2];
        __nv_bfloat162* pp = (__nv_bfloat162*)pk;
#pragma unroll
        for (int q = 0; q < 8; q++) pp[q] = __floats2bfloat162_rn(acc[2 * q], acc[2 * q + 1]);
        uint4* d = (uint4*)(ob + (size_t)v * 512);
        d[0] = pk[0]; d[1] = pk[1];
    }
}

// ---------------- mma.sync bf16 GEMM + fused bias/relu/W56-projection epilogue ----------------
__global__ void __launch_bounds__(256, 2) gemm_mma(
    const uint4* __restrict__ Ah, const uint4* __restrict__ Bh,
    const float* __restrict__ b4, float* __restrict__ outacc) {
    extern __shared__ char smem[];
    uint32_t sb = smem_to_u32(smem);
    int tid = threadIdx.x, lane = tid & 31, wid = tid >> 5;
    int wr = wid & 3, wc = wid >> 2;
    int row0 = blockIdx.y << 7, col0 = blockIdx.x << 7;

    auto load_chunk = [&](int kc, int stage) {
        uint32_t st = sb + stage * 16384;
#pragma unroll
        for (int i = tid; i < 512; i += 256) {
            int r = i >> 2, c = i & 3;
            uint32_t soff = SWZ(r * 64 + c * 16);
            size_t ga = (size_t)(row0 + r) * 64 + kc * 4 + c;
            size_t gb = (size_t)(col0 + r) * 64 + kc * 4 + c;
            CP_ASYNC16(st + soff,        (const void*)(Ah + ga));
            CP_ASYNC16(st + 8192 + soff, (const void*)(Bh + gb));
        }
    };

    load_chunk(0, 0); CP_COMMIT;
    load_chunk(1, 1); CP_COMMIT;
    load_chunk(2, 2); CP_COMMIT;

    float acc[2][8][4];
#pragma unroll
    for (int mt = 0; mt < 2; mt++)
#pragma unroll
        for (int nt = 0; nt < 8; nt++)
#pragma unroll
            for (int q = 0; q < 4; q++) acc[mt][nt][q] = 0.f;

    for (int kc = 0; kc < 16; kc++) {
        CP_WAIT_GROUP(2);
        __syncthreads();
        if (kc + 3 < 16) load_chunk(kc + 3, (kc + 3) & 3);
        CP_COMMIT;
        uint32_t base = sb + (kc & 3) * 16384;
#pragma unroll
        for (int ks = 0; ks < 2; ks++) {
            uint32_t ah[2][4];
#pragma unroll
            for (int mt = 0; mt < 2; mt++) {
                int r = wr * 32 + mt * 16 + (lane & 15);
                uint32_t off = SWZ(r * 64 + ks * 32 + ((lane >> 4) << 4));
                LDM4(ah[mt], base + off);
            }
#pragma unroll
            for (int nt2 = 0; nt2 < 4; nt2++) {
                int nrow = wc * 64 + nt2 * 16 + (lane & 7) + ((lane >> 4) << 3);
                uint32_t off = SWZ(nrow * 64 + ks * 32 + (((lane >> 3) & 1) << 4));
                uint32_t bhf[4];
                LDM4(bhf, base + 8192 + off);
#pragma unroll
                for (int h = 0; h < 2; h++) {
                    uint32_t bh2[2] = { bhf[2 * h], bhf[2 * h + 1] };
                    int nt = 2 * nt2 + h;
#pragma unroll
                    for (int mt = 0; mt < 2; mt++)
                        MMA16816(acc[mt][nt], ah[mt], bh2);
                }
            }
        }
    }

    float p[4][3];
#pragma unroll
    for (int r = 0; r < 4; r++) { p[r][0] = 0.f; p[r][1] = 0.f; p[r][2] = 0.f; }
    int R = row0 + wr * 32 + (lane >> 2);
    float s1r[4];
#pragma unroll
    for (int r = 0; r < 4; r++)
        s1r[r] = g_s1[(R + ((r >> 1) << 4) + ((r & 1) << 3)) & (NV - 1)];
#pragma unroll
    for (int mt = 0; mt < 2; mt++) {
#pragma unroll
        for (int nt = 0; nt < 8; nt++) {
            int c = col0 + wc * 64 + nt * 8 + ((lane & 3) << 1);
            float bw0 = g_b3W4[c],     bc0 = b4[c];
            float bw1 = g_b3W4[c + 1], bc1 = b4[c + 1];
            float wa0 = g_W56[c * 3 + 0], wa1 = g_W56[c * 3 + 1], wa2 = g_W56[c * 3 + 2];
            float wb0 = g_W56[(c + 1) * 3 + 0], wb1 = g_W56[(c + 1) * 3 + 1], wb2 = g_W56[(c + 1) * 3 + 2];
            int ra = mt * 2, rb = mt * 2 + 1;
            float u;
            u = fmaxf(0.f, acc[mt][nt][0] + s1r[ra] * bw0 + bc0);
            p[ra][0] = fmaf(u, wa0, p[ra][0]); p[ra][1] = fmaf(u, wa1, p[ra][1]); p[ra][2] = fmaf(u, wa2, p[ra][2]);
            u = fmaxf(0.f, acc[mt][nt][1] + s1r[ra] * bw1 + bc1);
            p[ra][0] = fmaf(u, wb0, p[ra][0]); p[ra][1] = fmaf(u, wb1, p[ra][1]); p[ra][2] = fmaf(u, wb2, p[ra][2]);
            u = fmaxf(0.f, acc[mt][nt][2] + s1r[rb] * bw0 + bc0);
            p[rb][0] = fmaf(u, wa0, p[rb][0]); p[rb][1] = fmaf(u, wa1, p[rb][1]); p[rb][2] = fmaf(u, wa2, p[rb][2]);
            u = fmaxf(0.f, acc[mt][nt][3] + s1r[rb] * bw1 + bc1);
            p[rb][0] = fmaf(u, wb0, p[rb][0]); p[rb][1] = fmaf(u, wb1, p[rb][1]); p[rb][2] = fmaf(u, wb2, p[rb][2]);
        }
    }
#pragma unroll
    for (int r = 0; r < 4; r++)
#pragma unroll
        for (int k = 0; k < 3; k++) {
            p[r][k] += __shfl_xor_sync(0xffffffffu, p[r][k], 1);
            p[r][k] += __shfl_xor_sync(0xffffffffu, p[r][k], 2);
        }
    if ((lane & 3) == 0) {
#pragma unroll
        for (int r = 0; r < 4; r++) {
            int m = R + ((r >> 1) << 4) + ((r & 1) << 3);
            atomicAdd(&outacc[(size_t)m * 3 + 0], p[r][0]);
            atomicAdd(&outacc[(size_t)m * 3 + 1], p[r][1]);
            atomicAdd(&outacc[(size_t)m * 3 + 2], p[r][2]);
        }
    }
}

// ---------------- FC head ----------------
__global__ void k_cinit3(const float* __restrict__ fcb1, const float* __restrict__ fcb2,
                         const float* __restrict__ fcb3) {
    int i = blockIdx.x * blockDim.x + threadIdx.x;
    if (i < 32 * 1024) {
        g_fch1[i] = fcb1[i & 1023];
        g_fch2[i] = fcb2[i & 1023];
    }
    if (i < 32 * 6144) g_fcout[i] = fcb3[i % 6144];
}

__global__ void __launch_bounds__(256) fcgemm_sk(const float* __restrict__ A,
                                                 const float* __restrict__ W,
                                                 float* __restrict__ C,
                                                 int K, int N, int Kc) {
    __shared__ float As[32][33];
    int tid = threadIdx.x;
    int o = blockIdx.x * 64 + (tid & 63);
    int bg = (tid >> 6) * 8;
    int k0base = blockIdx.y * Kc;
    float acc[8];
#pragma unroll
    for (int r = 0; r < 8; r++) acc[r] = 0.f;
    for (int k0 = k0base; k0 < k0base + Kc; k0 += 32) {
#pragma unroll
        for (int l = 0; l < 4; l++) {
            int idx = tid + 256 * l;
            int r = idx >> 5, kk = idx & 31;
            As[r][kk] = A[(size_t)r * K + k0 + kk];
        }
        __syncthreads();
#pragma unroll 8
        for (int kk = 0; kk < 32; kk++) {
            float w = W[(size_t)(k0 + kk) * N + o];
#pragma unroll
            for (int r = 0; r < 8; r++) acc[r] = fmaf(As[bg + r][kk], w, acc[r]);
        }
        __syncthreads();
    }
#pragma unroll
    for (int r = 0; r < 8; r++) atomicAdd(&C[(size_t)(bg + r) * N + o], acc[r]);
}

// ---------------- final: out = verts + 0.1*tanh(fcout) ----------------
__global__ void k_final(const float* __restrict__ verts, float* __restrict__ out) {
    int i = blockIdx.x * blockDim.x + threadIdx.x;
    if (i >= NB * NV * 3) return;
    out[i] = verts[i] + 0.1f * tanhf(g_fcout[i]);
}

// ---------------- host launcher ----------------
extern "C" void kernel_launch(void* const* d_in, const int* in_sizes, int n_in,
                              void* d_out, int out_size) {
    const float* verts = (const float*)d_in[0];
    const float* img   = (const float*)d_in[1];
    const int*   edge  = (const int*)d_in[2];
    const float* W1 = (const float*)d_in[3];   const float* b1 = (const float*)d_in[4];
    const float* W2 = (const float*)d_in[5];   const float* b2 = (const float*)d_in[6];
    const float* W3 = (const float*)d_in[7];   const float* b3 = (const float*)d_in[8];
    const float* W4 = (const float*)d_in[9];   const float* b4 = (const float*)d_in[10];
    const float* W5 = (const float*)d_in[11];  const float* b5 = (const float*)d_in[12];
    const float* W6 = (const float*)d_in[13];  const float* b6 = (const float*)d_in[14];
    const float* fcW1 = (const float*)d_in[15]; const float* fcb1 = (const float*)d_in[16];
    const float* fcW2 = (const float*)d_in[17]; const float* fcb2 = (const float*)d_in[18];
    const float* fcW3 = (const float*)d_in[19]; const float* fcb3 = (const float*)d_in[20];
    float* out = (float*)d_out;

    float *bufA, *bufB, *s3a, *s3b, *s3c, *imgstage, *imgterm, *b5W6;
    float *fch1, *fch2, *fcout;
    __nv_bfloat16 *w34t;
    cudaGetSymbolAddress((void**)&bufA, g_bufA);
    cudaGetSymbolAddress((void**)&bufB, g_bufB);
    cudaGetSymbolAddress((void**)&s3a, g_s3a);
    cudaGetSymbolAddress((void**)&s3b, g_s3b);
    cudaGetSymbolAddress((void**)&s3c, g_s3c);
    cudaGetSymbolAddress((void**)&imgstage, g_imgstage);
    cudaGetSymbolAddress((void**)&imgterm, g_imgterm);
    cudaGetSymbolAddress((void**)&w34t, g_W34T);
    cudaGetSymbolAddress((void**)&b5W6, g_b5W6);
    cudaGetSymbolAddress((void**)&fch1, g_fch1);
    cudaGetSymbolAddress((void**)&fch2, g_fch2);
    cudaGetSymbolAddress((void**)&fcout, g_fcout);

    __nv_bfloat16* x2h = (__nv_bfloat16*)bufA;
    __nv_bfloat16* t2h = (__nv_bfloat16*)bufB;

    static cudaStream_t sside = 0;
    static cudaEvent_t evFork = 0, evJoin = 0;
    static bool inited = false;
    if (!inited) {
        cudaStreamCreateWithFlags(&sside, cudaStreamNonBlocking);
        cudaEventCreateWithFlags(&evFork, cudaEventDisableTiming);
        cudaEventCreateWithFlags(&evJoin, cudaEventDisableTiming);
        cudaFuncSetAttribute(gemm_mma, cudaFuncAttributeMaxDynamicSharedMemorySize, 65536);
        cudaFuncSetAttribute(k_agg2hop, cudaFuncAttributeMaxDynamicSharedMemorySize, AG_SMEM);
        inited = true;
    }

    // ===== fork: side branch does ALL weight prep + FC-bias init + s3a zero =====
    cudaEventRecord(evFork, 0);
    cudaStreamWaitEvent(sside, evFork, 0);
    k_prepsmall<<<17, 256, 0, sside>>>(W1, W2, b1, b3, W4, W5, W6, b5);
    k_smallmm<<<64, 256, 0, sside>>>(img, W1 + 3 * 512, imgstage, NB, 512, 512, 512);
    k_smallmm<<<64, 256, 0, sside>>>(imgstage, W2, imgterm, NB, 512, 512, 512);
    sgemm64T<<<dim3(8, 8), 256, 0, sside>>>(W3, W4, 512, 512, 512);
    k_cinit3<<<768, 256, 0, sside>>>(fcb1, fcb2, fcb3);
    k_zero3a<<<768, 256, 0, sside>>>();
    cudaEventRecord(evJoin, sside);

    // ===== main branch: CSR setup + F=3 two-hop on vertices =====
    k_init<<<8, 256>>>();
    k_deg<<<48, 256>>>(edge);
    k_scan<<<1, 1024>>>();
    k_fill<<<56, 256>>>(edge);
    k_s1<<<8, 256>>>();
    k_s2<<<8, 256>>>();
    k_agg3<<<256, 256>>>(verts, s3c, NULL, NULL, 0);
    k_agg3<<<256, 256>>>(s3c, s3b, NULL, NULL, 0);

    // ===== join: x2 needs W12c/imgterm/b1W2; gemm needs W34T + zeroed s3a =====
    cudaStreamWaitEvent(0, evJoin, 0);
    k_x2<<<512, 128>>>(b2, x2h);

    // --- layers 3+4 ---
    k_agg2hop<<<dim3(32, 32), 1024, AG_SMEM>>>(x2h, t2h);
    gemm_mma<<<dim3(4, 512), 256, 65536>>>((const uint4*)t2h, (const uint4*)w34t, b4, s3a);

    // --- layers 5+6 remainder ---
    k_agg3<<<256, 256>>>(s3a, s3b, NULL, NULL, 0);
    k_agg3<<<256, 256>>>(s3b, s3c, b5W6, b6, 1);

    // --- FC head ---
    fcgemm_sk<<<dim3(16, 24), 256>>>(s3c, fcW1, fch1, 6144, 1024, 256);
    fcgemm_sk<<<dim3(16, 8), 256>>>(fch1, fcW2, fch2, 1024, 1024, 128);
    fcgemm_sk<<<dim3(96, 4), 256>>>(fch2, fcW3, fcout, 1024, 6144, 256);

    // --- output ---
    k_final<<<768, 256>>>(verts, out);
}

// round 15
// speedup vs baseline: 1.1462x; 1.0188x over previous
#include <cuda_runtime.h>
#include <cuda_bf16.h>
#include <cstdint>
#include <math.h>

#define NB 32
#define NV 2048
#define NEDGE 12288
#define NNZ (NEDGE + NV)   // 14336 (edges + self loops)

// ================= helpers (plain sm_103-safe) =================
__device__ __forceinline__ uint32_t smem_to_u32(const void* smem_ptr) {
    uint32_t addr;
    asm("{ .reg .u64 tmp; cvta.to.shared.u64 tmp, %1; cvt.u32.u64 %0, tmp; }"
        : "=r"(addr) : "l"(smem_ptr));
    return addr;
}
#define SWZ(o) ((o) ^ (((o) >> 3) & 0x70))
#define CP_ASYNC16(dst, src) \
    asm volatile("cp.async.cg.shared.global [%0], [%1], 16;" :: "r"(dst), "l"(src))
#define CP_COMMIT asm volatile("cp.async.commit_group;" ::: "memory")
#define CP_WAIT_GROUP(n) asm volatile("cp.async.wait_group %0;" :: "n"(n) : "memory")
#define LDM4(r, addr) \
    asm volatile("ldmatrix.sync.aligned.m8n8.x4.shared.b16 {%0,%1,%2,%3}, [%4];" \
        : "=r"((r)[0]), "=r"((r)[1]), "=r"((r)[2]), "=r"((r)[3]) : "r"(addr))
#define MMA16816(d, a, b) \
    asm volatile("mma.sync.aligned.m16n8k16.row.col.f32.bf16.bf16.f32 " \
        "{%0,%1,%2,%3}, {%4,%5,%6,%7}, {%8,%9}, {%0,%1,%2,%3};" \
        : "+f"((d)[0]), "+f"((d)[1]), "+f"((d)[2]), "+f"((d)[3]) \
        : "r"((a)[0]), "r"((a)[1]), "r"((a)[2]), "r"((a)[3]), "r"((b)[0]), "r"((b)[1]))

// ---------------- scratch (device globals; no allocation) ----------------
__device__ float g_bufA[(size_t)NB * NV * 512];   // x2 bf16 plane
__device__ float g_bufB[(size_t)NB * NV * 512];   // t2 bf16
__device__ float g_s3a[NB * NV * 3];
__device__ float g_s3b[NB * NV * 3];
__device__ float g_s3c[NB * NV * 3];
__device__ float g_imgstage[NB * 512];
__device__ float g_imgterm[NB * 512];
__device__ __nv_bfloat16 g_W34T[512 * 512];       // W34 transposed [N,K] bf16
__device__ float g_W12c[3 * 512];
__device__ float g_W56[512 * 3];
__device__ float g_b1W2[512];
__device__ float g_b3W4[512];
__device__ float g_b5W6[3];
__device__ float g_s1[NV];
__device__ float g_s2[NV];
__device__ float g_dinv[NV];
__device__ float g_nrm[NNZ];
__device__ int   g_rowptr[NV + 1];
__device__ int   g_cols[NNZ];
__device__ int   g_counts[NV];
__device__ int   g_fill[NV];
__device__ float g_fch1[NB * 1024];
__device__ float g_fch2[NB * 1024];
__device__ float g_fcout[NB * 6144];

// ---------------- graph/CSR setup ----------------
__global__ void k_init() {
    int i = blockIdx.x * blockDim.x + threadIdx.x;
    if (i < NV) { g_counts[i] = 1; g_fill[i] = 0; }
}
__global__ void k_deg(const int* __restrict__ edge) {
    int e = blockIdx.x * blockDim.x + threadIdx.x;
    if (e < NEDGE) atomicAdd(&g_counts[edge[NEDGE + e]], 1);
}
__global__ void k_scan() {
    __shared__ int p[1024];
    int t = threadIdx.x;
    int c0 = g_counts[2 * t], c1 = g_counts[2 * t + 1];
    g_dinv[2 * t]     = rsqrtf((float)c0);
    g_dinv[2 * t + 1] = rsqrtf((float)c1);
    p[t] = c0 + c1;
    __syncthreads();
    for (int off = 1; off < 1024; off <<= 1) {
        int v = (t >= off) ? p[t - off] : 0;
        __syncthreads();
        p[t] += v;
        __syncthreads();
    }
    int base = p[t] - (c0 + c1);
    g_rowptr[2 * t] = base;
    g_rowptr[2 * t + 1] = base + c0;
    if (t == 1023) g_rowptr[2048] = p[1023];
}
__global__ void k_fill(const int* __restrict__ edge) {
    int i = blockIdx.x * blockDim.x + threadIdx.x;
    if (i < NEDGE) {
        int s = edge[i], d = edge[NEDGE + i];
        int pos = g_rowptr[d] + atomicAdd(&g_fill[d], 1);
        g_cols[pos] = s;
        g_nrm[pos] = g_dinv[s] * g_dinv[d];
    } else if (i < NNZ) {
        int v = i - NEDGE;
        int pos = g_rowptr[v] + atomicAdd(&g_fill[v], 1);
        g_cols[pos] = v;
        g_nrm[pos] = g_dinv[v] * g_dinv[v];
    }
}
// s1 and s2 in one single-block kernel (two phases)
__global__ void __launch_bounds__(1024) k_s12() {
    int t = threadIdx.x;
    for (int v = t; v < NV; v += 1024) {
        float s = 0.f;
        for (int j = g_rowptr[v]; j < g_rowptr[v + 1]; j++) s += g_nrm[j];
        g_s1[v] = s;
    }
    __syncthreads();
    for (int v = t; v < NV; v += 1024) {
        float s = 0.f;
        for (int j = g_rowptr[v]; j < g_rowptr[v + 1]; j++) s += g_nrm[j] * g_s1[g_cols[j]];
        g_s2[v] = s;
    }
}
__global__ void k_zero3a() {
    int i = blockIdx.x * blockDim.x + threadIdx.x;
    if (i < NB * NV * 3) g_s3a[i] = 0.f;
}

// ---------------- generic small matmul (imgstage/imgterm; L2-resident) ----------------
__global__ void k_smallmm(const float* __restrict__ A, const float* __restrict__ Bw,
                          float* __restrict__ C, int M, int K, int N, int strideA) {
    int i = blockIdx.x * blockDim.x + threadIdx.x;
    if (i >= M * N) return;
    int m = i / N, o = i - m * N;
    float acc = 0.f;
    const float* a = A + (size_t)m * strideA;
    for (int k = 0; k < K; k++) acc += a[k] * Bw[(size_t)k * N + o];
    C[i] = acc;
}

// ---------------- fused tiny weight-prep ----------------
__global__ void k_prepsmall(const float* __restrict__ W1, const float* __restrict__ W2,
                            const float* __restrict__ b1, const float* __restrict__ b3,
                            const float* __restrict__ W4, const float* __restrict__ W5,
                            const float* __restrict__ W6, const float* __restrict__ b5) {
    int i = blockIdx.x * blockDim.x + threadIdx.x;
    if (i < 1536) {
        int m = i / 512, o = i - m * 512;
        float acc = 0.f;
        for (int k = 0; k < 512; k++) acc += W1[m * 512 + k] * W2[(size_t)k * 512 + o];
        g_W12c[i] = acc;
    } else if (i < 2048) {
        int o = i - 1536;
        float acc = 0.f;
        for (int k = 0; k < 512; k++) acc += b1[k] * W2[(size_t)k * 512 + o];
        g_b1W2[o] = acc;
    } else if (i < 2560) {
        int o = i - 2048;
        float acc = 0.f;
        for (int k = 0; k < 512; k++) acc += b3[k] * W4[(size_t)k * 512 + o];
        g_b3W4[o] = acc;
    } else if (i < 4096) {
        int j = i - 2560;
        int m = j / 3, o = j - m * 3;
        float acc = 0.f;
        for (int k = 0; k < 64; k++) acc += W5[m * 64 + k] * W6[k * 3 + o];
        g_W56[j] = acc;
    } else if (i < 4099) {
        int o = i - 4096;
        float acc = 0.f;
        for (int k = 0; k < 64; k++) acc += b5[k] * W6[k * 3 + o];
        g_b5W6[o] = acc;
    }
}

// ---------------- W34 = W3@W4, epilogue writes transposed bf16 directly ----------------
__global__ void __launch_bounds__(256) sgemm64T(const float* __restrict__ A,
                                                const float* __restrict__ Bw,
                                                int M, int N, int K) {
    __shared__ float As[16][64];
    __shared__ float Bs[16][68];
    int tid = threadIdx.x;
    int row0 = blockIdx.y * 64, col0 = blockIdx.x * 64;
    int aRow = tid >> 2, aCol = (tid & 3) * 4;
    int bRow = tid >> 4, bCol = (tid & 15) * 4;
    int tx = tid & 15, ty = tid >> 4;
    float acc[4][4];
#pragma unroll
    for (int i = 0; i < 4; i++)
#pragma unroll
        for (int j = 0; j < 4; j++) acc[i][j] = 0.f;
    for (int k0 = 0; k0 < K; k0 += 16) {
        float4 av = *(const float4*)&A[(size_t)(row0 + aRow) * K + k0 + aCol];
        float4 bv = *(const float4*)&Bw[(size_t)(k0 + bRow) * N + col0 + bCol];
        As[aCol + 0][aRow] = av.x;
        As[aCol + 1][aRow] = av.y;
        As[aCol + 2][aRow] = av.z;
        As[aCol + 3][aRow] = av.w;
        Bs[bRow][bCol + 0] = bv.x;
        Bs[bRow][bCol + 1] = bv.y;
        Bs[bRow][bCol + 2] = bv.z;
        Bs[bRow][bCol + 3] = bv.w;
        __syncthreads();
#pragma unroll
        for (int kk = 0; kk < 16; kk++) {
            float ar[4], br[4];
#pragma unroll
            for (int i = 0; i < 4; i++) ar[i] = As[kk][ty * 4 + i];
#pragma unroll
            for (int j = 0; j < 4; j++) br[j] = Bs[kk][tx * 4 + j];
#pragma unroll
            for (int i = 0; i < 4; i++)
#pragma unroll
                for (int j = 0; j < 4; j++) acc[i][j] = fmaf(ar[i], br[j], acc[i][j]);
        }
        __syncthreads();
    }
#pragma unroll
    for (int i = 0; i < 4; i++) {
        int krow = row0 + ty * 4 + i;
#pragma unroll
        for (int j = 0; j < 4; j++) {
            int ncol = col0 + tx * 4 + j;
            g_W34T[(size_t)ncol * 512 + krow] = __float2bfloat16(acc[i][j]);
        }
    }
}

// ---------------- aggregation, F=3 ----------------
__global__ void k_agg3(const float* __restrict__ in, float* __restrict__ out,
                       const float* __restrict__ biasA, const float* __restrict__ biasB,
                       int relu) {
    int i = blockIdx.x * blockDim.x + threadIdx.x;
    if (i >= NB * NV) return;
    int v = i & (NV - 1);
    int b = i >> 11;
    float a0 = 0.f, a1 = 0.f, a2 = 0.f;
    int beg = g_rowptr[v], end = g_rowptr[v + 1];
    const float* base = in + (size_t)b * NV * 3;
    for (int j = beg; j < end; j++) {
        int s = g_cols[j];
        float w = g_nrm[j];
        const float* p = base + s * 3;
        a0 = fmaf(w, p[0], a0);
        a1 = fmaf(w, p[1], a1);
        a2 = fmaf(w, p[2], a2);
    }
    if (biasA) {
        float s1v = g_s1[v];
        a0 += s1v * biasA[0] + biasB[0];
        a1 += s1v * biasA[1] + biasB[1];
        a2 += s1v * biasA[2] + biasB[2];
    }
    if (relu) { a0 = fmaxf(0.f, a0); a1 = fmaxf(0.f, a1); a2 = fmaxf(0.f, a2); }
    float* o = out + (size_t)i * 3;
    o[0] = a0; o[1] = a1; o[2] = a2;
}

// ---------------- x2 assembly -> bf16 plane (weights register-resident) ----------------
__global__ void __launch_bounds__(128) k_x2(const float* __restrict__ b2,
                                            __nv_bfloat16* __restrict__ ahi) {
    int og = threadIdx.x;            // quad index 0..127
    int b  = blockIdx.x >> 4;        // batch
    int vc = blockIdx.x & 15;        // vertex chunk of 128
    float4 w0 = ((const float4*)g_W12c)[0 * 128 + og];
    float4 w1 = ((const float4*)g_W12c)[1 * 128 + og];
    float4 w2 = ((const float4*)g_W12c)[2 * 128 + og];
    float4 it = ((const float4*)g_imgterm)[b * 128 + og];
    float4 bw = ((const float4*)g_b1W2)[og];
    float4 bb = ((const float4*)b2)[og];
    const float* s3 = g_s3b + ((size_t)b * NV + vc * 128) * 3;
    ushort4* outp = (ushort4*)ahi + ((size_t)b * NV + vc * 128) * 128 + og;
#pragma unroll 4
    for (int k = 0; k < 128; k++) {
        int v = vc * 128 + k;
        float a0 = s3[k * 3 + 0], a1 = s3[k * 3 + 1], a2 = s3[k * 3 + 2];
        float s1v = g_s1[v], s2v = g_s2[v];
        float r[4];
        r[0] = fmaxf(0.f, a0 * w0.x + a1 * w1.x + a2 * w2.x + s2v * it.x + s1v * bw.x + bb.x);
        r[1] = fmaxf(0.f, a0 * w0.y + a1 * w1.y + a2 * w2.y + s2v * it.y + s1v * bw.y + bb.y);
        r[2] = fmaxf(0.f, a0 * w0.z + a1 * w1.z + a2 * w2.z + s2v * it.z + s1v * bw.z + bb.z);
        r[3] = fmaxf(0.f, a0 * w0.w + a1 * w1.w + a2 * w2.w + s2v * it.w + s1v * bw.w + bb.w);
        ushort4 hv;
        unsigned short* hp = &hv.x;
#pragma unroll
        for (int q = 0; q < 4; q++) {
            __nv_bfloat16 h = __float2bfloat16(r[q]);
            hp[q] = *(unsigned short*)&h;
        }
        outp[(size_t)k * 128] = hv;
    }
}

// ---------------- fused two-hop aggregation: t2 = A^2(x2), smem-resident ----------------
#define AG_STRIDE 48
#define AG_SMEM   (NV * AG_STRIDE)   // 98304
__global__ void __launch_bounds__(1024) k_agg2hop(const __nv_bfloat16* __restrict__ x2,
                                                  __nv_bfloat16* __restrict__ t2) {
    extern __shared__ char sm[];
    int f0 = blockIdx.x * 16;
    int b  = blockIdx.y;
    int t  = threadIdx.x;
    const __nv_bfloat16* xb = x2 + (size_t)b * NV * 512 + f0;
    __nv_bfloat16* ob = t2 + (size_t)b * NV * 512 + f0;
#pragma unroll
    for (int r = 0; r < 2; r++) {
        int v = t + r * 1024;
        const uint4* src = (const uint4*)(xb + (size_t)v * 512);
        uint4* d = (uint4*)(sm + v * AG_STRIDE);
        d[0] = src[0]; d[1] = src[1];
    }
    __syncthreads();
    uint4 keep[2][2];
#pragma unroll
    for (int r = 0; r < 2; r++) {
        int v = t + r * 1024;
        float acc[16];
#pragma unroll
        for (int q = 0; q < 16; q++) acc[q] = 0.f;
        int beg = g_rowptr[v], end = g_rowptr[v + 1];
        for (int j = beg; j < end; j++) {
            int s = g_cols[j];
            float w = g_nrm[j];
            uint4 q0 = *(const uint4*)(sm + s * AG_STRIDE);
            uint4 q1 = *(const uint4*)(sm + s * AG_STRIDE + 16);
            const __nv_bfloat162* h0 = (const __nv_bfloat162*)&q0;
            const __nv_bfloat162* h1 = (const __nv_bfloat162*)&q1;
#pragma unroll
            for (int q = 0; q < 4; q++) {
                float2 f = __bfloat1622float2(h0[q]);
                acc[2 * q]     = fmaf(w, f.x, acc[2 * q]);
                acc[2 * q + 1] = fmaf(w, f.y, acc[2 * q + 1]);
                float2 g = __bfloat1622float2(h1[q]);
                acc[8 + 2 * q]     = fmaf(w, g.x, acc[8 + 2 * q]);
                acc[8 + 2 * q + 1] = fmaf(w, g.y, acc[8 + 2 * q + 1]);
            }
        }
        __nv_bfloat162* kp = (__nv_bfloat162*)keep[r];
#pragma unroll
        for (int q = 0; q < 8; q++) kp[q] = __floats2bfloat162_rn(acc[2 * q], acc[2 * q + 1]);
    }
    __syncthreads();
#pragma unroll
    for (int r = 0; r < 2; r++) {
        int v = t + r * 1024;
        uint4* d = (uint4*)(sm + v * AG_STRIDE);
        d[0] = keep[r][0]; d[1] = keep[r][1];
    }
    __syncthreads();
#pragma unroll
    for (int r = 0; r < 2; r++) {
        int v = t + r * 1024;
        float acc[16];
#pragma unroll
        for (int q = 0; q < 16; q++) acc[q] = 0.f;
        int beg = g_rowptr[v], end = g_rowptr[v + 1];
        for (int j = beg; j < end; j++) {
            int s = g_cols[j];
            float w = g_nrm[j];
            uint4 q0 = *(const uint4*)(sm + s * AG_STRIDE);
            uint4 q1 = *(const uint4*)(sm + s * AG_STRIDE + 16);
            const __nv_bfloat162* h0 = (const __nv_bfloat162*)&q0;
            const __nv_bfloat162* h1 = (const __nv_bfloat162*)&q1;
#pragma unroll
            for (int q = 0; q < 4; q++) {
                float2 f = __bfloat1622float2(h0[q]);
                acc[2 * q]     = fmaf(w, f.x, acc[2 * q]);
                acc[2 * q + 1] = fmaf(w, f.y, acc[2 * q + 1]);
                float2 g = __bfloat1622float2(h1[q]);
                acc[8 + 2 * q]     = fmaf(w, g.x, acc[8 + 2 * q]);
                acc[8 + 2 * q + 1] = fmaf(w, g.y, acc[8 + 2 * q + 1]);
            }
        }
        uint4 pk[2];
        __nv_bfloat162* pp = (__nv_bfloat162*)pk;
#pragma unroll
        for (int q = 0; q < 8; q++) pp[q] = __floats2bfloat162_rn(acc[2 * q], acc[2 * q + 1]);
        uint4* d = (uint4*)(ob + (size_t)v * 512);
        d[0] = pk[0]; d[1] = pk[1];
    }
}

// ---------------- mma.sync bf16 GEMM + fused bias/relu/W56-projection epilogue ----------------
__global__ void __launch_bounds__(256, 2) gemm_mma(
    const uint4* __restrict__ Ah, const uint4* __restrict__ Bh,
    const float* __restrict__ b4, float* __restrict__ outacc) {
    extern __shared__ char smem[];
    uint32_t sb = smem_to_u32(smem);
    int tid = threadIdx.x, lane = tid & 31, wid = tid >> 5;
    int wr = wid & 3, wc = wid >> 2;
    int row0 = blockIdx.y << 7, col0 = blockIdx.x << 7;

    auto load_chunk = [&](int kc, int stage) {
        uint32_t st = sb + stage * 16384;
#pragma unroll
        for (int i = tid; i < 512; i += 256) {
            int r = i >> 2, c = i & 3;
            uint32_t soff = SWZ(r * 64 + c * 16);
            size_t ga = (size_t)(row0 + r) * 64 + kc * 4 + c;
            size_t gb = (size_t)(col0 + r) * 64 + kc * 4 + c;
            CP_ASYNC16(st + soff,        (const void*)(Ah + ga));
            CP_ASYNC16(st + 8192 + soff, (const void*)(Bh + gb));
        }
    };

    load_chunk(0, 0); CP_COMMIT;
    load_chunk(1, 1); CP_COMMIT;
    load_chunk(2, 2); CP_COMMIT;

    float acc[2][8][4];
#pragma unroll
    for (int mt = 0; mt < 2; mt++)
#pragma unroll
        for (int nt = 0; nt < 8; nt++)
#pragma unroll
            for (int q = 0; q < 4; q++) acc[mt][nt][q] = 0.f;

    for (int kc = 0; kc < 16; kc++) {
        CP_WAIT_GROUP(2);
        __syncthreads();
        if (kc + 3 < 16) load_chunk(kc + 3, (kc + 3) & 3);
        CP_COMMIT;
        uint32_t base = sb + (kc & 3) * 16384;
#pragma unroll
        for (int ks = 0; ks < 2; ks++) {
            uint32_t ah[2][4];
#pragma unroll
            for (int mt = 0; mt < 2; mt++) {
                int r = wr * 32 + mt * 16 + (lane & 15);
                uint32_t off = SWZ(r * 64 + ks * 32 + ((lane >> 4) << 4));
                LDM4(ah[mt], base + off);
            }
#pragma unroll
            for (int nt2 = 0; nt2 < 4; nt2++) {
                int nrow = wc * 64 + nt2 * 16 + (lane & 7) + ((lane >> 4) << 3);
                uint32_t off = SWZ(nrow * 64 + ks * 32 + (((lane >> 3) & 1) << 4));
                uint32_t bhf[4];
                LDM4(bhf, base + 8192 + off);
#pragma unroll
                for (int h = 0; h < 2; h++) {
                    uint32_t bh2[2] = { bhf[2 * h], bhf[2 * h + 1] };
                    int nt = 2 * nt2 + h;
#pragma unroll
                    for (int mt = 0; mt < 2; mt++)
                        MMA16816(acc[mt][nt], ah[mt], bh2);
                }
            }
        }
    }

    float p[4][3];
#pragma unroll
    for (int r = 0; r < 4; r++) { p[r][0] = 0.f; p[r][1] = 0.f; p[r][2] = 0.f; }
    int R = row0 + wr * 32 + (lane >> 2);
    float s1r[4];
#pragma unroll
    for (int r = 0; r < 4; r++)
        s1r[r] = g_s1[(R + ((r >> 1) << 4) + ((r & 1) << 3)) & (NV - 1)];
#pragma unroll
    for (int mt = 0; mt < 2; mt++) {
#pragma unroll
        for (int nt = 0; nt < 8; nt++) {
            int c = col0 + wc * 64 + nt * 8 + ((lane & 3) << 1);
            float bw0 = g_b3W4[c],     bc0 = b4[c];
            float bw1 = g_b3W4[c + 1], bc1 = b4[c + 1];
            float wa0 = g_W56[c * 3 + 0], wa1 = g_W56[c * 3 + 1], wa2 = g_W56[c * 3 + 2];
            float wb0 = g_W56[(c + 1) * 3 + 0], wb1 = g_W56[(c + 1) * 3 + 1], wb2 = g_W56[(c + 1) * 3 + 2];
            int ra = mt * 2, rb = mt * 2 + 1;
            float u;
            u = fmaxf(0.f, acc[mt][nt][0] + s1r[ra] * bw0 + bc0);
            p[ra][0] = fmaf(u, wa0, p[ra][0]); p[ra][1] = fmaf(u, wa1, p[ra][1]); p[ra][2] = fmaf(u, wa2, p[ra][2]);
            u = fmaxf(0.f, acc[mt][nt][1] + s1r[ra] * bw1 + bc1);
            p[ra][0] = fmaf(u, wb0, p[ra][0]); p[ra][1] = fmaf(u, wb1, p[ra][1]); p[ra][2] = fmaf(u, wb2, p[ra][2]);
            u = fmaxf(0.f, acc[mt][nt][2] + s1r[rb] * bw0 + bc0);
            p[rb][0] = fmaf(u, wa0, p[rb][0]); p[rb][1] = fmaf(u, wa1, p[rb][1]); p[rb][2] = fmaf(u, wa2, p[rb][2]);
            u = fmaxf(0.f, acc[mt][nt][3] + s1r[rb] * bw1 + bc1);
            p[rb][0] = fmaf(u, wb0, p[rb][0]); p[rb][1] = fmaf(u, wb1, p[rb][1]); p[rb][2] = fmaf(u, wb2, p[rb][2]);
        }
    }
#pragma unroll
    for (int r = 0; r < 4; r++)
#pragma unroll
        for (int k = 0; k < 3; k++) {
            p[r][k] += __shfl_xor_sync(0xffffffffu, p[r][k], 1);
            p[r][k] += __shfl_xor_sync(0xffffffffu, p[r][k], 2);
        }
    if ((lane & 3) == 0) {
#pragma unroll
        for (int r = 0; r < 4; r++) {
            int m = R + ((r >> 1) << 4) + ((r & 1) << 3);
            atomicAdd(&outacc[(size_t)m * 3 + 0], p[r][0]);
            atomicAdd(&outacc[(size_t)m * 3 + 1], p[r][1]);
            atomicAdd(&outacc[(size_t)m * 3 + 2], p[r][2]);
        }
    }
}

// ---------------- FC head ----------------
__global__ void k_cinit3(const float* __restrict__ fcb1, const float* __restrict__ fcb2,
                         const float* __restrict__ fcb3) {
    int i = blockIdx.x * blockDim.x + threadIdx.x;
    if (i < 32 * 1024) {
        g_fch1[i] = fcb1[i & 1023];
        g_fch2[i] = fcb2[i & 1023];
    }
    if (i < 32 * 6144) g_fcout[i] = fcb3[i % 6144];
}

__global__ void __launch_bounds__(256) fcgemm_sk(const float* __restrict__ A,
                                                 const float* __restrict__ W,
                                                 float* __restrict__ C,
                                                 int K, int N, int Kc) {
    __shared__ float As[32][33];
    int tid = threadIdx.x;
    int o = blockIdx.x * 64 + (tid & 63);
    int bg = (tid >> 6) * 8;
    int k0base = blockIdx.y * Kc;
    float acc[8];
#pragma unroll
    for (int r = 0; r < 8; r++) acc[r] = 0.f;
    for (int k0 = k0base; k0 < k0base + Kc; k0 += 32) {
#pragma unroll
        for (int l = 0; l < 4; l++) {
            int idx = tid + 256 * l;
            int r = idx >> 5, kk = idx & 31;
            As[r][kk] = A[(size_t)r * K + k0 + kk];
        }
        __syncthreads();
#pragma unroll 8
        for (int kk = 0; kk < 32; kk++) {
            float w = W[(size_t)(k0 + kk) * N + o];
#pragma unroll
            for (int r = 0; r < 8; r++) acc[r] = fmaf(As[bg + r][kk], w, acc[r]);
        }
        __syncthreads();
    }
#pragma unroll
    for (int r = 0; r < 8; r++) atomicAdd(&C[(size_t)(bg + r) * N + o], acc[r]);
}

// ---------------- final: out = verts + 0.1*tanh(fcout) ----------------
__global__ void k_final(const float* __restrict__ verts, float* __restrict__ out) {
    int i = blockIdx.x * blockDim.x + threadIdx.x;
    if (i >= NB * NV * 3) return;
    out[i] = verts[i] + 0.1f * tanhf(g_fcout[i]);
}

// ---------------- host launcher ----------------
extern "C" void kernel_launch(void* const* d_in, const int* in_sizes, int n_in,
                              void* d_out, int out_size) {
    const float* verts = (const float*)d_in[0];
    const float* img   = (const float*)d_in[1];
    const int*   edge  = (const int*)d_in[2];
    const float* W1 = (const float*)d_in[3];   const float* b1 = (const float*)d_in[4];
    const float* W2 = (const float*)d_in[5];   const float* b2 = (const float*)d_in[6];
    const float* W3 = (const float*)d_in[7];   const float* b3 = (const float*)d_in[8];
    const float* W4 = (const float*)d_in[9];   const float* b4 = (const float*)d_in[10];
    const float* W5 = (const float*)d_in[11];  const float* b5 = (const float*)d_in[12];
    const float* W6 = (const float*)d_in[13];  const float* b6 = (const float*)d_in[14];
    const float* fcW1 = (const float*)d_in[15]; const float* fcb1 = (const float*)d_in[16];
    const float* fcW2 = (const float*)d_in[17]; const float* fcb2 = (const float*)d_in[18];
    const float* fcW3 = (const float*)d_in[19]; const float* fcb3 = (const float*)d_in[20];
    float* out = (float*)d_out;

    float *bufA, *bufB, *s3a, *s3b, *s3c, *imgstage, *imgterm, *b5W6;
    float *fch1, *fch2, *fcout;
    __nv_bfloat16 *w34t;
    cudaGetSymbolAddress((void**)&bufA, g_bufA);
    cudaGetSymbolAddress((void**)&bufB, g_bufB);
    cudaGetSymbolAddress((void**)&s3a, g_s3a);
    cudaGetSymbolAddress((void**)&s3b, g_s3b);
    cudaGetSymbolAddress((void**)&s3c, g_s3c);
    cudaGetSymbolAddress((void**)&imgstage, g_imgstage);
    cudaGetSymbolAddress((void**)&imgterm, g_imgterm);
    cudaGetSymbolAddress((void**)&w34t, g_W34T);
    cudaGetSymbolAddress((void**)&b5W6, g_b5W6);
    cudaGetSymbolAddress((void**)&fch1, g_fch1);
    cudaGetSymbolAddress((void**)&fch2, g_fch2);
    cudaGetSymbolAddress((void**)&fcout, g_fcout);

    __nv_bfloat16* x2h = (__nv_bfloat16*)bufA;
    __nv_bfloat16* t2h = (__nv_bfloat16*)bufB;

    static cudaStream_t sside = 0;
    static cudaEvent_t evFork = 0, evJoin1 = 0, evJoin2 = 0;
    static bool inited = false;
    if (!inited) {
        cudaStreamCreateWithFlags(&sside, cudaStreamNonBlocking);
        cudaEventCreateWithFlags(&evFork, cudaEventDisableTiming);
        cudaEventCreateWithFlags(&evJoin1, cudaEventDisableTiming);
        cudaEventCreateWithFlags(&evJoin2, cudaEventDisableTiming);
        cudaFuncSetAttribute(gemm_mma, cudaFuncAttributeMaxDynamicSharedMemorySize, 65536);
        cudaFuncSetAttribute(k_agg2hop, cudaFuncAttributeMaxDynamicSharedMemorySize, AG_SMEM);
        inited = true;
    }

    // ===== fork: side branch =====
    cudaEventRecord(evFork, 0);
    cudaStreamWaitEvent(sside, evFork, 0);
    // stage 1 (gates k_x2): W12c/b1W2/b3W4/W56/b5W6 + imgterm
    k_prepsmall<<<17, 256, 0, sside>>>(W1, W2, b1, b3, W4, W5, W6, b5);
    k_smallmm<<<64, 256, 0, sside>>>(img, W1 + 3 * 512, imgstage, NB, 512, 512, 512);
    k_smallmm<<<64, 256, 0, sside>>>(imgstage, W2, imgterm, NB, 512, 512, 512);
    cudaEventRecord(evJoin1, sside);
    // stage 2 (gates gemm_mma / FC head): W34T + s3a zero + FC bias init
    sgemm64T<<<dim3(8, 8), 256, 0, sside>>>(W3, W4, 512, 512, 512);
    k_zero3a<<<768, 256, 0, sside>>>();
    k_cinit3<<<768, 256, 0, sside>>>(fcb1, fcb2, fcb3);
    cudaEventRecord(evJoin2, sside);

    // ===== main branch: CSR setup + F=3 two-hop on vertices =====
    k_init<<<8, 256>>>();
    k_deg<<<48, 256>>>(edge);
    k_scan<<<1, 1024>>>();
    k_fill<<<56, 256>>>(edge);
    k_s12<<<1, 1024>>>();
    k_agg3<<<256, 256>>>(verts, s3c, NULL, NULL, 0);
    k_agg3<<<256, 256>>>(s3c, s3b, NULL, NULL, 0);

    // ===== join 1: x2 needs W12c/imgterm/b1W2 =====
    cudaStreamWaitEvent(0, evJoin1, 0);
    k_x2<<<512, 128>>>(b2, x2h);

    // --- layers 3+4 ---
    k_agg2hop<<<dim3(32, 32), 1024, AG_SMEM>>>(x2h, t2h);
    // ===== join 2: gemm needs W34T + zeroed s3a =====
    cudaStreamWaitEvent(0, evJoin2, 0);
    gemm_mma<<<dim3(4, 512), 256, 65536>>>((const uint4*)t2h, (const uint4*)w34t, b4, s3a);

    // --- layers 5+6 remainder ---
    k_agg3<<<256, 256>>>(s3a, s3b, NULL, NULL, 0);
    k_agg3<<<256, 256>>>(s3b, s3c, b5W6, b6, 1);

    // --- FC head ---
    fcgemm_sk<<<dim3(16, 24), 256>>>(s3c, fcW1, fch1, 6144, 1024, 256);
    fcgemm_sk<<<dim3(16, 8), 256>>>(fch1, fcW2, fch2, 1024, 1024, 128);
    fcgemm_sk<<<dim3(96, 4), 256>>>(fch2, fcW3, fcout, 1024, 6144, 256);

    // --- output ---
    k_final<<<768, 256>>>(verts, out);
}